// round 1
// baseline (speedup 1.0000x reference)
#include <cuda_runtime.h>

#define HW   4096
#define CIN  256
#define CH   128   // half channels
#define NB   4

// Scratch (allocation-free rule: __device__ globals)
__device__ float g_n1[NB*CH*HW];   // [b][128][4096]  (== Q viewed [4096][128])
__device__ float g_n2[NB*CH*HW];   // K: [b][128][4096]
__device__ float g_n3[NB*CH*HW];   // V viewed [4096][128]
__device__ float g_res[NB*CH*HW];  // res written [4096][128], read as [128][4096]

// ---------------------------------------------------------------------------
// Kernel 1: QKV projections. out[f][p] = sum_c W[f][c] * X[c][p]
// M=128, N=4096, K=256, 12 (b,s) pairs. 64x64 tile, 256 thr, 4x4 microtile.
// ---------------------------------------------------------------------------
__global__ void qkv_gemm_kernel(const float* __restrict__ x,
                                const float* __restrict__ w1,
                                const float* __restrict__ w2,
                                const float* __restrict__ w3) {
    const int b = blockIdx.z / 3, s = blockIdx.z % 3;
    const float* W = (s == 0) ? w1 : (s == 1) ? w2 : w3;
    float* out = ((s == 0) ? g_n1 : (s == 1) ? g_n2 : g_n3) + (size_t)b * CH * HW;
    const float* X = x + (size_t)b * CIN * HW;
    const int f0 = blockIdx.y * 64, p0 = blockIdx.x * 64;

    __shared__ float Ws[32][68];  // Ws[c][f] (transposed for float4 reads)
    __shared__ float Xs[32][68];  // Xs[c][p]

    const int tid = threadIdx.x;
    const int tx = tid & 15, ty = tid >> 4;

    float acc[4][4];
#pragma unroll
    for (int q = 0; q < 4; q++)
#pragma unroll
        for (int t = 0; t < 4; t++) acc[q][t] = 0.f;

    for (int c0 = 0; c0 < CIN; c0 += 32) {
#pragma unroll
        for (int i = tid; i < 64 * 32; i += 256) {
            int f = i >> 5, c = i & 31;
            Ws[c][f] = W[(f0 + f) * CIN + c0 + c];
        }
#pragma unroll
        for (int i = tid; i < 32 * 64; i += 256) {
            int c = i >> 6, p = i & 63;
            Xs[c][p] = X[(c0 + c) * HW + p0 + p];
        }
        __syncthreads();
#pragma unroll
        for (int c = 0; c < 32; c++) {
            float4 wv = *(const float4*)&Ws[c][ty * 4];
            float4 xv = *(const float4*)&Xs[c][tx * 4];
            float wr[4] = {wv.x, wv.y, wv.z, wv.w};
            float xr[4] = {xv.x, xv.y, xv.z, xv.w};
#pragma unroll
            for (int q = 0; q < 4; q++)
#pragma unroll
                for (int t = 0; t < 4; t++) acc[q][t] += wr[q] * xr[t];
        }
        __syncthreads();
    }
#pragma unroll
    for (int q = 0; q < 4; q++) {
        float4 v = make_float4(acc[q][0], acc[q][1], acc[q][2], acc[q][3]);
        *(float4*)&out[(size_t)(f0 + ty * 4 + q) * HW + p0 + tx * 4] = v;
    }
}

// ---------------------------------------------------------------------------
// Kernel 2: fused flash attention (fp32, online softmax).
// Q = g_n1 as [4096][128], K = g_n2 as [128][4096], V = g_n3 as [4096][128].
// BM=64 rows/CTA, BN=64 per iteration, 256 threads.
// Smem: Qs[128][68] + Ks[128][68] (Ps[64][68] aliases Ks) + Vs[64][132].
// ---------------------------------------------------------------------------
#define QS_STRIDE 68
#define VS_STRIDE 132
#define SMEM_FLOATS (2 * 128 * QS_STRIDE + 64 * VS_STRIDE)

__global__ void flash_kernel() {
    extern __shared__ float sm[];
    float* Qs = sm;                       // [128][68]  Qs[c][r]
    float* Ks = sm + 128 * QS_STRIDE;     // [128][68]  Ks[c][j]; later Ps[j][r]
    float* Vs = sm + 2 * 128 * QS_STRIDE; // [64][132]  Vs[j][d]

    const int b = blockIdx.y;
    const int i0 = blockIdx.x * 64;
    const float* Q = g_n1 + (size_t)b * CH * HW;
    const float* K = g_n2 + (size_t)b * CH * HW;
    const float* V = g_n3 + (size_t)b * CH * HW;
    float* R = g_res + (size_t)b * CH * HW;

    const int tid = threadIdx.x;
    const int tx = tid & 15, ty = tid >> 4;

    // Load Q tile, transposed: Qs[c][r] = Q[i0+r][c]
#pragma unroll
    for (int i = tid; i < 64 * 128; i += 256) {
        int r = i >> 7, c = i & 127;
        Qs[c * QS_STRIDE + r] = Q[(size_t)(i0 + r) * 128 + c];
    }

    float m[4], l[4], o[4][8];
#pragma unroll
    for (int q = 0; q < 4; q++) {
        m[q] = -1e30f;
        l[q] = 0.f;
#pragma unroll
        for (int d = 0; d < 8; d++) o[q][d] = 0.f;
    }

    for (int j0 = 0; j0 < HW; j0 += 64) {
        // K tile: Ks[c][j] = K[c][j0+j]
#pragma unroll
        for (int i = tid; i < 128 * 64; i += 256) {
            int c = i >> 6, j = i & 63;
            Ks[c * QS_STRIDE + j] = K[(size_t)c * HW + j0 + j];
        }
        // V tile: Vs[j][d] = V[j0+j][d]
#pragma unroll
        for (int i = tid; i < 64 * 128; i += 256) {
            int j = i >> 7, d = i & 127;
            Vs[j * VS_STRIDE + d] = V[(size_t)(j0 + j) * 128 + d];
        }
        __syncthreads();

        // S = Q @ K tile: thread computes rows ty*4..+3, cols tx*4..+3
        float s[4][4];
#pragma unroll
        for (int q = 0; q < 4; q++)
#pragma unroll
            for (int t = 0; t < 4; t++) s[q][t] = 0.f;
#pragma unroll
        for (int c = 0; c < 128; c++) {
            float4 qv = *(const float4*)&Qs[c * QS_STRIDE + ty * 4];
            float4 kv = *(const float4*)&Ks[c * QS_STRIDE + tx * 4];
            float qr[4] = {qv.x, qv.y, qv.z, qv.w};
            float kr[4] = {kv.x, kv.y, kv.z, kv.w};
#pragma unroll
            for (int q = 0; q < 4; q++)
#pragma unroll
                for (int t = 0; t < 4; t++) s[q][t] += qr[q] * kr[t];
        }
        __syncthreads();  // everyone done reading Ks before P overwrites it

        // online softmax: rows live across the 16 tx-lanes of each half-warp
        float scl[4];
#pragma unroll
        for (int q = 0; q < 4; q++) {
            float mt = fmaxf(fmaxf(s[q][0], s[q][1]), fmaxf(s[q][2], s[q][3]));
#pragma unroll
            for (int msk = 8; msk >= 1; msk >>= 1)
                mt = fmaxf(mt, __shfl_xor_sync(0xffffffffu, mt, msk, 16));
            float mn = fmaxf(m[q], mt);
            scl[q] = __expf(m[q] - mn);
            float rs = 0.f;
#pragma unroll
            for (int t = 0; t < 4; t++) {
                s[q][t] = __expf(s[q][t] - mn);
                rs += s[q][t];
            }
#pragma unroll
            for (int msk = 8; msk >= 1; msk >>= 1)
                rs += __shfl_xor_sync(0xffffffffu, rs, msk, 16);
            l[q] = l[q] * scl[q] + rs;
            m[q] = mn;
            // store P transposed into the Ks buffer: Ps[j][r]
#pragma unroll
            for (int t = 0; t < 4; t++)
                Ks[(tx * 4 + t) * QS_STRIDE + ty * 4 + q] = s[q][t];
            // rescale accumulator
#pragma unroll
            for (int d = 0; d < 8; d++) o[q][d] *= scl[q];
        }
        __syncthreads();

        // O += P @ V tile: thread owns rows ty*4..+3, cols tx*8..+7
#pragma unroll
        for (int j = 0; j < 64; j++) {
            float4 pv = *(const float4*)&Ks[j * QS_STRIDE + ty * 4];
            float4 v0 = *(const float4*)&Vs[j * VS_STRIDE + tx * 8];
            float4 v1 = *(const float4*)&Vs[j * VS_STRIDE + tx * 8 + 4];
            float pr[4] = {pv.x, pv.y, pv.z, pv.w};
            float vr[8] = {v0.x, v0.y, v0.z, v0.w, v1.x, v1.y, v1.z, v1.w};
#pragma unroll
            for (int q = 0; q < 4; q++)
#pragma unroll
                for (int d = 0; d < 8; d++) o[q][d] += pr[q] * vr[d];
        }
        __syncthreads();  // protect Ks/Vs before next iteration's loads
    }

    // finalize: divide by l, store res as [4096][128]
#pragma unroll
    for (int q = 0; q < 4; q++) {
        float inv = 1.0f / l[q];
        int r = i0 + ty * 4 + q;
        float4 a = make_float4(o[q][0] * inv, o[q][1] * inv, o[q][2] * inv, o[q][3] * inv);
        float4 c = make_float4(o[q][4] * inv, o[q][5] * inv, o[q][6] * inv, o[q][7] * inv);
        *(float4*)&R[(size_t)r * 128 + tx * 8] = a;
        *(float4*)&R[(size_t)r * 128 + tx * 8 + 4] = c;
    }
}

// ---------------------------------------------------------------------------
// Kernel 3: out = BN(w4 @ res_view) + x.  res_view = g_res as [128][4096].
// M=256, N=4096, K=128 per batch.
// ---------------------------------------------------------------------------
__global__ void out_gemm_kernel(const float* __restrict__ x,
                                const float* __restrict__ w4,
                                const float* __restrict__ gamma,
                                const float* __restrict__ beta,
                                const float* __restrict__ rmean,
                                const float* __restrict__ rvar,
                                float* __restrict__ out) {
    const int b = blockIdx.z;
    const float* R = g_res + (size_t)b * CH * HW;  // [128][4096] view
    const int o0 = blockIdx.y * 64, p0 = blockIdx.x * 64;

    __shared__ float Ws[32][68];  // Ws[c][o]
    __shared__ float Rs[32][68];  // Rs[c][p]

    const int tid = threadIdx.x;
    const int tx = tid & 15, ty = tid >> 4;

    float acc[4][4];
#pragma unroll
    for (int q = 0; q < 4; q++)
#pragma unroll
        for (int t = 0; t < 4; t++) acc[q][t] = 0.f;

    for (int c0 = 0; c0 < CH; c0 += 32) {
#pragma unroll
        for (int i = tid; i < 64 * 32; i += 256) {
            int f = i >> 5, c = i & 31;
            Ws[c][f] = w4[(o0 + f) * CH + c0 + c];
        }
#pragma unroll
        for (int i = tid; i < 32 * 64; i += 256) {
            int c = i >> 6, p = i & 63;
            Rs[c][p] = R[(size_t)(c0 + c) * HW + p0 + p];
        }
        __syncthreads();
#pragma unroll
        for (int c = 0; c < 32; c++) {
            float4 wv = *(const float4*)&Ws[c][ty * 4];
            float4 rv = *(const float4*)&Rs[c][tx * 4];
            float wr[4] = {wv.x, wv.y, wv.z, wv.w};
            float rr[4] = {rv.x, rv.y, rv.z, rv.w};
#pragma unroll
            for (int q = 0; q < 4; q++)
#pragma unroll
                for (int t = 0; t < 4; t++) acc[q][t] += wr[q] * rr[t];
        }
        __syncthreads();
    }

#pragma unroll
    for (int q = 0; q < 4; q++) {
        int oc = o0 + ty * 4 + q;
        float sc = gamma[oc] * rsqrtf(rvar[oc] + 1e-5f);
        float mu = rmean[oc], bt = beta[oc];
        size_t base = (size_t)b * CIN * HW + (size_t)oc * HW + p0 + tx * 4;
        float4 xv = *(const float4*)&x[base];
        float4 r;
        r.x = (acc[q][0] - mu) * sc + bt + xv.x;
        r.y = (acc[q][1] - mu) * sc + bt + xv.y;
        r.z = (acc[q][2] - mu) * sc + bt + xv.z;
        r.w = (acc[q][3] - mu) * sc + bt + xv.w;
        *(float4*)&out[base] = r;
    }
}

// ---------------------------------------------------------------------------
extern "C" void kernel_launch(void* const* d_in, const int* in_sizes, int n_in,
                              void* d_out, int out_size) {
    const float* x     = (const float*)d_in[0];
    const float* w1    = (const float*)d_in[1];
    const float* w2    = (const float*)d_in[2];
    const float* w3    = (const float*)d_in[3];
    const float* w4    = (const float*)d_in[4];
    const float* gamma = (const float*)d_in[5];
    const float* beta  = (const float*)d_in[6];
    const float* rmean = (const float*)d_in[7];
    const float* rvar  = (const float*)d_in[8];
    float* out = (float*)d_out;

    // QKV projections: 64 p-tiles x 2 f-tiles x (4 batches * 3 weights)
    qkv_gemm_kernel<<<dim3(64, 2, 12), 256>>>(x, w1, w2, w3);

    // Fused flash attention
    size_t smem = SMEM_FLOATS * sizeof(float);  // ~101 KB -> needs opt-in
    cudaFuncSetAttribute(flash_kernel,
                         cudaFuncAttributeMaxDynamicSharedMemorySize, (int)smem);
    flash_kernel<<<dim3(64, 4), 256, smem>>>();

    // Output projection + BN + residual
    out_gemm_kernel<<<dim3(64, 4, 4), 256>>>(x, w4, gamma, beta, rmean, rvar, out);
}

// round 2
// speedup vs baseline: 1.3326x; 1.3326x over previous
#include <cuda_runtime.h>

#define HW   4096
#define CIN  256
#define CH   128
#define NB   4

// Scratch (allocation-free rule: __device__ globals)
__device__ float g_n1[NB*CH*HW];   // Q viewed [4096][128]
__device__ float g_n2[NB*CH*HW];   // K: [128][4096]
__device__ float g_n3[NB*CH*HW];   // V viewed [4096][128]
__device__ float g_res[NB*CH*HW];  // res [4096][128], read as [128][4096]

// ---- packed f32x2 helpers (FFMA2 path, sm_100+) -----------------------------
__device__ __forceinline__ unsigned long long pk2(float x, float y) {
    unsigned long long r;
    asm("mov.b64 %0, {%1, %2};" : "=l"(r) : "f"(x), "f"(y));
    return r;
}
__device__ __forceinline__ float2 upk2(unsigned long long v) {
    float2 r;
    asm("mov.b64 {%0, %1}, %2;" : "=f"(r.x), "=f"(r.y) : "l"(v));
    return r;
}
__device__ __forceinline__ void ffma2(unsigned long long& d,
                                      unsigned long long a,
                                      unsigned long long b) {
    asm("fma.rn.f32x2 %0, %1, %2, %0;" : "+l"(d) : "l"(a), "l"(b));
}
__device__ __forceinline__ unsigned long long fmul2(unsigned long long a,
                                                    unsigned long long b) {
    unsigned long long d;
    asm("mul.rn.f32x2 %0, %1, %2;" : "=l"(d) : "l"(a), "l"(b));
    return d;
}

// ---------------------------------------------------------------------------
// Kernel 1: QKV projections. out[f][p] = sum_c W[f][c] * X[c][p]
// M=128, N=4096, K=256. Tile 128x128, 256 thr, 8x8 microtile, FFMA2.
// ---------------------------------------------------------------------------
__global__ __launch_bounds__(256) void qkv_gemm_kernel(
        const float* __restrict__ x,
        const float* __restrict__ w1,
        const float* __restrict__ w2,
        const float* __restrict__ w3) {
    const int b = blockIdx.z / 3, s = blockIdx.z % 3;
    const float* W = (s == 0) ? w1 : (s == 1) ? w2 : w3;
    float* out = ((s == 0) ? g_n1 : (s == 1) ? g_n2 : g_n3) + (size_t)b * CH * HW;
    const float* X = x + (size_t)b * CIN * HW;
    const int p0 = blockIdx.x * 128;

    __shared__ float Ws[32 * 132];  // Ws[c][f]
    __shared__ float Xs[32 * 132];  // Xs[c][p]

    const int tid = threadIdx.x;
    const int tx = tid & 15, ty = tid >> 4;
    const int r0 = ty * 8, pc = tx * 8;

    unsigned long long acc[4][8];
#pragma unroll
    for (int q = 0; q < 4; q++)
#pragma unroll
        for (int t = 0; t < 8; t++) acc[q][t] = 0ull;

    for (int c0 = 0; c0 < CIN; c0 += 32) {
#pragma unroll
        for (int i = tid; i < 1024; i += 256) {
            int f = i >> 3, c4 = (i & 7) * 4;
            float4 wv = *(const float4*)&W[f * CIN + c0 + c4];
            Ws[(c4 + 0) * 132 + f] = wv.x;
            Ws[(c4 + 1) * 132 + f] = wv.y;
            Ws[(c4 + 2) * 132 + f] = wv.z;
            Ws[(c4 + 3) * 132 + f] = wv.w;
        }
#pragma unroll
        for (int i = tid; i < 1024; i += 256) {
            int c = i >> 5, p4 = (i & 31) * 4;
            *(float4*)&Xs[c * 132 + p4] = *(const float4*)&X[(size_t)(c0 + c) * HW + p0 + p4];
        }
        __syncthreads();
#pragma unroll
        for (int c = 0; c < 32; c++) {
            float4 wa = *(const float4*)&Ws[c * 132 + r0];
            float4 wb = *(const float4*)&Ws[c * 132 + r0 + 4];
            float4 xa = *(const float4*)&Xs[c * 132 + pc];
            float4 xb = *(const float4*)&Xs[c * 132 + pc + 4];
            unsigned long long wp[4] = {pk2(wa.x, wa.y), pk2(wa.z, wa.w),
                                        pk2(wb.x, wb.y), pk2(wb.z, wb.w)};
            float xr[8] = {xa.x, xa.y, xa.z, xa.w, xb.x, xb.y, xb.z, xb.w};
#pragma unroll
            for (int t = 0; t < 8; t++) {
                unsigned long long xbcast = pk2(xr[t], xr[t]);
#pragma unroll
                for (int q = 0; q < 4; q++) ffma2(acc[q][t], wp[q], xbcast);
            }
        }
        __syncthreads();
    }
#pragma unroll
    for (int q = 0; q < 4; q++) {
        float o0[8], o1[8];
#pragma unroll
        for (int t = 0; t < 8; t++) {
            float2 v = upk2(acc[q][t]);
            o0[t] = v.x; o1[t] = v.y;
        }
        int f = r0 + 2 * q;
        *(float4*)&out[(size_t)f * HW + p0 + pc]     = make_float4(o0[0], o0[1], o0[2], o0[3]);
        *(float4*)&out[(size_t)f * HW + p0 + pc + 4] = make_float4(o0[4], o0[5], o0[6], o0[7]);
        *(float4*)&out[(size_t)(f + 1) * HW + p0 + pc]     = make_float4(o1[0], o1[1], o1[2], o1[3]);
        *(float4*)&out[(size_t)(f + 1) * HW + p0 + pc + 4] = make_float4(o1[4], o1[5], o1[6], o1[7]);
    }
}

// ---------------------------------------------------------------------------
// Kernel 2: fused flash attention (fp32, FFMA2, online softmax).
// BM=BN=128, 256 threads, 8x8 microtile.
// Smem: Qs[128][132] + Ks[128][132] (Ps aliases Ks) + Vs[128][132] = 198 KB.
// ---------------------------------------------------------------------------
#define FS 132
#define FLASH_SMEM (3 * 128 * FS * 4)

__global__ __launch_bounds__(256, 1) void flash_kernel() {
    extern __shared__ float sm[];
    float* Qs = sm;                 // Qs[c][r]
    float* Ks = sm + 128 * FS;      // Ks[c][j]; later Ps[j][r]
    float* Vs = sm + 2 * 128 * FS;  // Vs[j][d]

    const int b = blockIdx.y;
    const int i0 = blockIdx.x * 128;
    const float* Q = g_n1 + (size_t)b * CH * HW;
    const float* K = g_n2 + (size_t)b * CH * HW;
    const float* V = g_n3 + (size_t)b * CH * HW;
    float* R = g_res + (size_t)b * CH * HW;

    const int tid = threadIdx.x;
    const int tx = tid & 15, ty = tid >> 4;
    const int r0 = ty * 8, cc = tx * 8;

    // Load Q tile transposed: Qs[c][r] = Q[i0+r][c]
#pragma unroll
    for (int i = tid; i < 4096; i += 256) {
        int r = i >> 5, c4 = (i & 31) * 4;
        float4 v = *(const float4*)&Q[(size_t)(i0 + r) * 128 + c4];
        Qs[(c4 + 0) * FS + r] = v.x;
        Qs[(c4 + 1) * FS + r] = v.y;
        Qs[(c4 + 2) * FS + r] = v.z;
        Qs[(c4 + 3) * FS + r] = v.w;
    }

    float m[8], l[8];
    unsigned long long ov[4][8];
#pragma unroll
    for (int h = 0; h < 8; h++) { m[h] = -1e30f; l[h] = 0.f; }
#pragma unroll
    for (int q = 0; q < 4; q++)
#pragma unroll
        for (int t = 0; t < 8; t++) ov[q][t] = 0ull;

    for (int j0 = 0; j0 < HW; j0 += 128) {
        // K tile: Ks[c][j] = K[c][j0+j]
#pragma unroll
        for (int i = tid; i < 4096; i += 256) {
            int c = i >> 5, j4 = (i & 31) * 4;
            *(float4*)&Ks[c * FS + j4] = *(const float4*)&K[(size_t)c * HW + j0 + j4];
        }
        // V tile: Vs[j][d] = V[j0+j][d]
#pragma unroll
        for (int i = tid; i < 4096; i += 256) {
            int j = i >> 5, d4 = (i & 31) * 4;
            *(float4*)&Vs[j * FS + d4] = *(const float4*)&V[(size_t)(j0 + j) * 128 + d4];
        }
        __syncthreads();

        // ---- S = Q @ K tile (8 rows x 8 cols per thread, row-pair packed)
        unsigned long long sa[4][8];
#pragma unroll
        for (int q = 0; q < 4; q++)
#pragma unroll
            for (int t = 0; t < 8; t++) sa[q][t] = 0ull;
#pragma unroll 4
        for (int c = 0; c < 128; c++) {
            float4 qa = *(const float4*)&Qs[c * FS + r0];
            float4 qb = *(const float4*)&Qs[c * FS + r0 + 4];
            float4 ka = *(const float4*)&Ks[c * FS + cc];
            float4 kb = *(const float4*)&Ks[c * FS + cc + 4];
            unsigned long long qp[4] = {pk2(qa.x, qa.y), pk2(qa.z, qa.w),
                                        pk2(qb.x, qb.y), pk2(qb.z, qb.w)};
            float kr[8] = {ka.x, ka.y, ka.z, ka.w, kb.x, kb.y, kb.z, kb.w};
#pragma unroll
            for (int t = 0; t < 8; t++) {
                unsigned long long kbc = pk2(kr[t], kr[t]);
#pragma unroll
                for (int q = 0; q < 4; q++) ffma2(sa[q][t], qp[q], kbc);
            }
        }
        __syncthreads();  // done reading Ks; Ps will overwrite it

        // ---- online softmax (rows spread over 16 tx-lanes per half-warp)
#pragma unroll
        for (int q = 0; q < 4; q++) {
            float2 sv[8];
            float mx0 = -1e30f, mx1 = -1e30f;
#pragma unroll
            for (int t = 0; t < 8; t++) {
                sv[t] = upk2(sa[q][t]);
                mx0 = fmaxf(mx0, sv[t].x);
                mx1 = fmaxf(mx1, sv[t].y);
            }
#pragma unroll
            for (int msk = 8; msk >= 1; msk >>= 1) {
                mx0 = fmaxf(mx0, __shfl_xor_sync(0xffffffffu, mx0, msk, 16));
                mx1 = fmaxf(mx1, __shfl_xor_sync(0xffffffffu, mx1, msk, 16));
            }
            float mn0 = fmaxf(m[2 * q], mx0);
            float mn1 = fmaxf(m[2 * q + 1], mx1);
            float sc0 = __expf(m[2 * q] - mn0);
            float sc1 = __expf(m[2 * q + 1] - mn1);
            m[2 * q] = mn0; m[2 * q + 1] = mn1;
            float rs0 = 0.f, rs1 = 0.f;
#pragma unroll
            for (int t = 0; t < 8; t++) {
                sv[t].x = __expf(sv[t].x - mn0);
                sv[t].y = __expf(sv[t].y - mn1);
                rs0 += sv[t].x; rs1 += sv[t].y;
            }
#pragma unroll
            for (int msk = 8; msk >= 1; msk >>= 1) {
                rs0 += __shfl_xor_sync(0xffffffffu, rs0, msk, 16);
                rs1 += __shfl_xor_sync(0xffffffffu, rs1, msk, 16);
            }
            l[2 * q]     = l[2 * q] * sc0 + rs0;
            l[2 * q + 1] = l[2 * q + 1] * sc1 + rs1;
            unsigned long long scp = pk2(sc0, sc1);
#pragma unroll
            for (int t = 0; t < 8; t++) ov[q][t] = fmul2(ov[q][t], scp);
            // store P transposed: Ps[j][r], row-pairs contiguous -> STS.64
#pragma unroll
            for (int t = 0; t < 8; t++)
                *(float2*)&Ks[(cc + t) * FS + r0 + 2 * q] = sv[t];
        }
        __syncthreads();

        // ---- O += P @ V tile (same 8x8 structure; d-cols = tx*8..+7)
#pragma unroll 4
        for (int j = 0; j < 128; j++) {
            float4 pa = *(const float4*)&Ks[j * FS + r0];
            float4 pb = *(const float4*)&Ks[j * FS + r0 + 4];
            float4 va = *(const float4*)&Vs[j * FS + cc];
            float4 vb = *(const float4*)&Vs[j * FS + cc + 4];
            unsigned long long pp[4] = {pk2(pa.x, pa.y), pk2(pa.z, pa.w),
                                        pk2(pb.x, pb.y), pk2(pb.z, pb.w)};
            float vr[8] = {va.x, va.y, va.z, va.w, vb.x, vb.y, vb.z, vb.w};
#pragma unroll
            for (int t = 0; t < 8; t++) {
                unsigned long long vbc = pk2(vr[t], vr[t]);
#pragma unroll
                for (int q = 0; q < 4; q++) ffma2(ov[q][t], pp[q], vbc);
            }
        }
        __syncthreads();  // protect Ks/Vs before next iteration's loads
    }

    // ---- finalize: divide by l, store res as [4096][128]
    float inv[8];
#pragma unroll
    for (int h = 0; h < 8; h++) inv[h] = 1.0f / l[h];
#pragma unroll
    for (int q = 0; q < 4; q++) {
        float o0[8], o1[8];
#pragma unroll
        for (int t = 0; t < 8; t++) {
            float2 v = upk2(ov[q][t]);
            o0[t] = v.x * inv[2 * q];
            o1[t] = v.y * inv[2 * q + 1];
        }
        int r = i0 + r0 + 2 * q;
        *(float4*)&R[(size_t)r * 128 + cc]     = make_float4(o0[0], o0[1], o0[2], o0[3]);
        *(float4*)&R[(size_t)r * 128 + cc + 4] = make_float4(o0[4], o0[5], o0[6], o0[7]);
        *(float4*)&R[(size_t)(r + 1) * 128 + cc]     = make_float4(o1[0], o1[1], o1[2], o1[3]);
        *(float4*)&R[(size_t)(r + 1) * 128 + cc + 4] = make_float4(o1[4], o1[5], o1[6], o1[7]);
    }
}

// ---------------------------------------------------------------------------
// Kernel 3: out = BN(w4 @ res_view) + x.  res_view = g_res as [128][4096].
// M=256, N=4096, K=128. Tile 128x128, FFMA2 8x8.
// ---------------------------------------------------------------------------
__global__ __launch_bounds__(256) void out_gemm_kernel(
        const float* __restrict__ x,
        const float* __restrict__ w4,
        const float* __restrict__ gamma,
        const float* __restrict__ beta,
        const float* __restrict__ rmean,
        const float* __restrict__ rvar,
        float* __restrict__ out) {
    const int b = blockIdx.z;
    const float* R = g_res + (size_t)b * CH * HW;  // [128][4096] view
    const int o0 = blockIdx.y * 128, p0 = blockIdx.x * 128;

    __shared__ float Ws[32 * 132];  // Ws[c][o]
    __shared__ float Rs[32 * 132];  // Rs[c][p]

    const int tid = threadIdx.x;
    const int tx = tid & 15, ty = tid >> 4;
    const int r0 = ty * 8, pc = tx * 8;

    unsigned long long acc[4][8];
#pragma unroll
    for (int q = 0; q < 4; q++)
#pragma unroll
        for (int t = 0; t < 8; t++) acc[q][t] = 0ull;

    for (int c0 = 0; c0 < CH; c0 += 32) {
#pragma unroll
        for (int i = tid; i < 1024; i += 256) {
            int f = i >> 3, c4 = (i & 7) * 4;
            float4 wv = *(const float4*)&w4[(o0 + f) * CH + c0 + c4];
            Ws[(c4 + 0) * 132 + f] = wv.x;
            Ws[(c4 + 1) * 132 + f] = wv.y;
            Ws[(c4 + 2) * 132 + f] = wv.z;
            Ws[(c4 + 3) * 132 + f] = wv.w;
        }
#pragma unroll
        for (int i = tid; i < 1024; i += 256) {
            int c = i >> 5, p4 = (i & 31) * 4;
            *(float4*)&Rs[c * 132 + p4] = *(const float4*)&R[(size_t)(c0 + c) * HW + p0 + p4];
        }
        __syncthreads();
#pragma unroll
        for (int c = 0; c < 32; c++) {
            float4 wa = *(const float4*)&Ws[c * 132 + r0];
            float4 wb = *(const float4*)&Ws[c * 132 + r0 + 4];
            float4 ra = *(const float4*)&Rs[c * 132 + pc];
            float4 rb = *(const float4*)&Rs[c * 132 + pc + 4];
            unsigned long long wp[4] = {pk2(wa.x, wa.y), pk2(wa.z, wa.w),
                                        pk2(wb.x, wb.y), pk2(wb.z, wb.w)};
            float rr[8] = {ra.x, ra.y, ra.z, ra.w, rb.x, rb.y, rb.z, rb.w};
#pragma unroll
            for (int t = 0; t < 8; t++) {
                unsigned long long rbc = pk2(rr[t], rr[t]);
#pragma unroll
                for (int q = 0; q < 4; q++) ffma2(acc[q][t], wp[q], rbc);
            }
        }
        __syncthreads();
    }

#pragma unroll
    for (int q = 0; q < 4; q++) {
        float o0v[8], o1v[8];
#pragma unroll
        for (int t = 0; t < 8; t++) {
            float2 v = upk2(acc[q][t]);
            o0v[t] = v.x; o1v[t] = v.y;
        }
#pragma unroll
        for (int h = 0; h < 2; h++) {
            int oc = o0 + r0 + 2 * q + h;
            float sc = gamma[oc] * rsqrtf(rvar[oc] + 1e-5f);
            float mu = rmean[oc], bt = beta[oc];
            const float* vv = h ? o1v : o0v;
            size_t base = (size_t)b * CIN * HW + (size_t)oc * HW + p0 + pc;
            float4 xv0 = *(const float4*)&x[base];
            float4 xv1 = *(const float4*)&x[base + 4];
            float4 w0, w1;
            w0.x = (vv[0] - mu) * sc + bt + xv0.x;
            w0.y = (vv[1] - mu) * sc + bt + xv0.y;
            w0.z = (vv[2] - mu) * sc + bt + xv0.z;
            w0.w = (vv[3] - mu) * sc + bt + xv0.w;
            w1.x = (vv[4] - mu) * sc + bt + xv1.x;
            w1.y = (vv[5] - mu) * sc + bt + xv1.y;
            w1.z = (vv[6] - mu) * sc + bt + xv1.z;
            w1.w = (vv[7] - mu) * sc + bt + xv1.w;
            *(float4*)&out[base]     = w0;
            *(float4*)&out[base + 4] = w1;
        }
    }
}

// ---------------------------------------------------------------------------
extern "C" void kernel_launch(void* const* d_in, const int* in_sizes, int n_in,
                              void* d_out, int out_size) {
    const float* x     = (const float*)d_in[0];
    const float* w1    = (const float*)d_in[1];
    const float* w2    = (const float*)d_in[2];
    const float* w3    = (const float*)d_in[3];
    const float* w4    = (const float*)d_in[4];
    const float* gamma = (const float*)d_in[5];
    const float* beta  = (const float*)d_in[6];
    const float* rmean = (const float*)d_in[7];
    const float* rvar  = (const float*)d_in[8];
    float* out = (float*)d_out;

    // QKV projections: 32 p-tiles x (4 batches * 3 weights)
    qkv_gemm_kernel<<<dim3(32, 1, 12), 256>>>(x, w1, w2, w3);

    // Fused flash attention: 32 row-tiles x 4 batches, 198 KB smem
    cudaFuncSetAttribute(flash_kernel,
                         cudaFuncAttributeMaxDynamicSharedMemorySize, FLASH_SMEM);
    flash_kernel<<<dim3(32, 4), 256, FLASH_SMEM>>>();

    // Output projection + BN + residual
    out_gemm_kernel<<<dim3(32, 2, 4), 256>>>(x, w4, gamma, beta, rmean, rvar, out);
}

// round 6
// speedup vs baseline: 2.3916x; 1.7946x over previous
#include <cuda_runtime.h>
#include <cuda_bf16.h>
#include <cstdint>

#define HW   4096
#define CIN  256
#define CH   128
#define NB   4
#define BNT  64    // KV tile

// Scratch (__device__ globals; allocation-free rule)
__device__ __nv_bfloat16 g_qh[NB*CH*HW], g_ql[NB*CH*HW];  // Q: [i=4096][c=128] raw view
__device__ __nv_bfloat16 g_kh[NB*CH*HW], g_kl[NB*CH*HW];  // K: [j=4096][c=128] (transposed)
__device__ __nv_bfloat16 g_vh[NB*CH*HW], g_vl[NB*CH*HW];  // V: [d=128][j=4096]
__device__ float g_res[NB*CH*HW];                          // res [i][d] flat = [128][4096] view

// ---- packed f32x2 helpers (FFMA2) ------------------------------------------
__device__ __forceinline__ unsigned long long pk2(float x, float y) {
    unsigned long long r;
    asm("mov.b64 %0, {%1, %2};" : "=l"(r) : "f"(x), "f"(y));
    return r;
}
__device__ __forceinline__ float2 upk2(unsigned long long v) {
    float2 r;
    asm("mov.b64 {%0, %1}, %2;" : "=f"(r.x), "=f"(r.y) : "l"(v));
    return r;
}
__device__ __forceinline__ void ffma2(unsigned long long& d,
                                      unsigned long long a,
                                      unsigned long long b) {
    asm("fma.rn.f32x2 %0, %1, %2, %0;" : "+l"(d) : "l"(a), "l"(b));
}

// ---- bf16 hi/lo split ------------------------------------------------------
__device__ __forceinline__ uint32_t b2u(__nv_bfloat162 v) {
    return *reinterpret_cast<uint32_t*>(&v);
}
__device__ __forceinline__ void bfsplit2(float a, float b,
                                         uint32_t& hi, uint32_t& lo) {
    __nv_bfloat162 h = __floats2bfloat162_rn(a, b);
    float ra = a - __low2float(h);
    float rb = b - __high2float(h);
    __nv_bfloat162 l = __floats2bfloat162_rn(ra, rb);
    hi = b2u(h); lo = b2u(l);
}

__device__ __forceinline__ uint32_t smem_u32(const void* p) {
    uint32_t a;
    asm("{ .reg .u64 t; cvta.to.shared.u64 t, %1; cvt.u32.u64 %0, t; }"
        : "=r"(a) : "l"(p));
    return a;
}

// ---- mma.sync / ldmatrix wrappers (portable sm_80+ PTX) --------------------
__device__ __forceinline__ void ldsm4(uint32_t* r, uint32_t addr) {
    asm volatile("ldmatrix.sync.aligned.m8n8.x4.shared.b16 {%0,%1,%2,%3}, [%4];"
                 : "=r"(r[0]), "=r"(r[1]), "=r"(r[2]), "=r"(r[3]) : "r"(addr));
}
__device__ __forceinline__ void mma16816(float* d, const uint32_t* a,
                                         uint32_t b0, uint32_t b1) {
    asm volatile(
        "mma.sync.aligned.m16n8k16.row.col.f32.bf16.bf16.f32 "
        "{%0,%1,%2,%3}, {%4,%5,%6,%7}, {%8,%9}, {%0,%1,%2,%3};"
        : "+f"(d[0]), "+f"(d[1]), "+f"(d[2]), "+f"(d[3])
        : "r"(a[0]), "r"(a[1]), "r"(a[2]), "r"(a[3]), "r"(b0), "r"(b1));
}

// ---- swizzled smem offsets (16B chunk XOR by row) --------------------------
// 256B rows (128 bf16 cols)
__device__ __forceinline__ uint32_t off256(int r, int c) {
    return (uint32_t)(r * 256 + ((((c >> 3) ^ r) & 7) << 4) + ((c >> 3) & ~7) * 16 + (c & 7) * 2);
}
// 128B rows (64 bf16 cols)
__device__ __forceinline__ uint32_t off128b(int r, int c) {
    return (uint32_t)(r * 128 + (((c >> 3) ^ (r & 7)) << 4) + (c & 7) * 2);
}

// smem layout (bytes)
#define SQH 0
#define SQL 32768
#define SKH 65536
#define SKL 81920
#define SVH 98304
#define SVL 114688
#define SPH 131072
#define SPL 147456
#define SLS 163840
#define FLASH_SMEM (SLS + 2048)

// ---------------------------------------------------------------------------
// Kernel 1: QKV projections (FFMA2), epilogue emits bf16 hi/lo layouts.
// ---------------------------------------------------------------------------
__global__ __launch_bounds__(256) void qkv_gemm_kernel(
        const float* __restrict__ x,
        const float* __restrict__ w1,
        const float* __restrict__ w2,
        const float* __restrict__ w3) {
    const int b = blockIdx.z / 3, s = blockIdx.z % 3;
    const float* W = (s == 0) ? w1 : (s == 1) ? w2 : w3;
    const float* X = x + (size_t)b * CIN * HW;
    const int p0 = blockIdx.x * 128, bx = blockIdx.x;
    const size_t bo = (size_t)b * CH * HW;

    __shared__ float Ws[32 * 132];
    __shared__ float Xs[32 * 132];

    const int tid = threadIdx.x;
    const int tx = tid & 15, ty = tid >> 4;
    const int r0 = ty * 8, pc = tx * 8;

    unsigned long long acc[4][8];
#pragma unroll
    for (int q = 0; q < 4; q++)
#pragma unroll
        for (int t = 0; t < 8; t++) acc[q][t] = 0ull;

    for (int c0 = 0; c0 < CIN; c0 += 32) {
#pragma unroll
        for (int i = tid; i < 1024; i += 256) {
            int f = i >> 3, c4 = (i & 7) * 4;
            float4 wv = *(const float4*)&W[f * CIN + c0 + c4];
            Ws[(c4 + 0) * 132 + f] = wv.x;
            Ws[(c4 + 1) * 132 + f] = wv.y;
            Ws[(c4 + 2) * 132 + f] = wv.z;
            Ws[(c4 + 3) * 132 + f] = wv.w;
        }
#pragma unroll
        for (int i = tid; i < 1024; i += 256) {
            int c = i >> 5, p4 = (i & 31) * 4;
            *(float4*)&Xs[c * 132 + p4] = *(const float4*)&X[(size_t)(c0 + c) * HW + p0 + p4];
        }
        __syncthreads();
#pragma unroll
        for (int c = 0; c < 32; c++) {
            float4 wa = *(const float4*)&Ws[c * 132 + r0];
            float4 wb = *(const float4*)&Ws[c * 132 + r0 + 4];
            float4 xa = *(const float4*)&Xs[c * 132 + pc];
            float4 xb = *(const float4*)&Xs[c * 132 + pc + 4];
            unsigned long long wp[4] = {pk2(wa.x, wa.y), pk2(wa.z, wa.w),
                                        pk2(wb.x, wb.y), pk2(wb.z, wb.w)};
            float xr[8] = {xa.x, xa.y, xa.z, xa.w, xb.x, xb.y, xb.z, xb.w};
#pragma unroll
            for (int t = 0; t < 8; t++) {
                unsigned long long xbc = pk2(xr[t], xr[t]);
#pragma unroll
                for (int q = 0; q < 4; q++) ffma2(acc[q][t], wp[q], xbc);
            }
        }
        __syncthreads();
    }

    if (s == 0) {
        __nv_bfloat16* QH = g_qh + bo;
        __nv_bfloat16* QL = g_ql + bo;
#pragma unroll
        for (int q = 0; q < 4; q++) {
            float o0[8], o1[8];
#pragma unroll
            for (int t = 0; t < 8; t++) {
                float2 v = upk2(acc[q][t]);
                o0[t] = v.x; o1[t] = v.y;
            }
#pragma unroll
            for (int h = 0; h < 2; h++) {
                const float* vv = h ? o1 : o0;
                int f = r0 + 2 * q + h;
                uint32_t hh[4], ll[4];
#pragma unroll
                for (int u = 0; u < 4; u++) bfsplit2(vv[2*u], vv[2*u+1], hh[u], ll[u]);
                *(uint4*)&QH[(size_t)f * HW + p0 + pc] = *(uint4*)hh;
                *(uint4*)&QL[(size_t)f * HW + p0 + pc] = *(uint4*)ll;
            }
        }
    } else if (s == 1) {
        __nv_bfloat16* KH = g_kh + bo;
        __nv_bfloat16* KL = g_kl + bo;
#pragma unroll
        for (int t = 0; t < 8; t++) {
            int p = p0 + pc + t;
            float fv[8];
#pragma unroll
            for (int q = 0; q < 4; q++) {
                float2 v = upk2(acc[q][t]);
                fv[2*q] = v.x; fv[2*q+1] = v.y;
            }
            uint32_t hh[4], ll[4];
#pragma unroll
            for (int u = 0; u < 4; u++) bfsplit2(fv[2*u], fv[2*u+1], hh[u], ll[u]);
            *(uint4*)&KH[(size_t)p * 128 + r0] = *(uint4*)hh;
            *(uint4*)&KL[(size_t)p * 128 + r0] = *(uint4*)ll;
        }
    } else {
        __nv_bfloat16* VH = g_vh + bo;
        __nv_bfloat16* VL = g_vl + bo;
#pragma unroll
        for (int q = 0; q < 4; q++) {
            float o0[8], o1[8];
#pragma unroll
            for (int t = 0; t < 8; t++) {
                float2 v = upk2(acc[q][t]);
                o0[t] = v.x; o1[t] = v.y;
            }
#pragma unroll
            for (int h = 0; h < 2; h++) {
                const float* vv = h ? o1 : o0;
                int f = r0 + 2 * q + h;
                int j = f * 32 + bx;
#pragma unroll
                for (int t = 0; t < 8; t++) {
                    int d = pc + t;
                    __nv_bfloat16 hb = __float2bfloat16_rn(vv[t]);
                    float lof = vv[t] - __bfloat162float(hb);
                    VH[(size_t)d * HW + j] = hb;
                    VL[(size_t)d * HW + j] = __float2bfloat16_rn(lof);
                }
            }
        }
    }
}

// ---------------------------------------------------------------------------
// Kernel 2: flash attention via mma.sync bf16x3, no-max softmax.
// 8 warps = 2(m)x4(n). BM=128, BN=64, D=128.
// ---------------------------------------------------------------------------
__global__ __launch_bounds__(256, 1) void flash_mma() {
    extern __shared__ char sm[];
    const uint32_t smb = smem_u32(sm);
    const int tid = threadIdx.x, lane = tid & 31, wid = tid >> 5;
    const int wm = wid & 1, wn = wid >> 1;
    const int b = blockIdx.y, i0 = blockIdx.x * 128;
    const size_t bo = (size_t)b * CH * HW;
    const __nv_bfloat16 *Qh = g_qh + bo, *Ql = g_ql + bo;
    const __nv_bfloat16 *Kh = g_kh + bo, *Kl = g_kl + bo;
    const __nv_bfloat16 *Vh = g_vh + bo, *Vl = g_vl + bo;

    // ldmatrix lane geometry
    const int lr = lane & 15;          // row within 16
    const int lk = (lane >> 4) * 8;    // 16B col half
    const int qr = lane >> 2;          // accum row-within-8
    const int qc = (lane & 3) * 2;     // accum col pair

    // ---- load persistent Q tile (hi/lo) ----
#pragma unroll 4
    for (int i = tid; i < 2048; i += 256) {
        int r = i >> 4, c8 = (i & 15) * 8;
        uint32_t off = off256(r, c8);
        *(uint4*)(sm + SQH + off) = *(const uint4*)(Qh + (size_t)(i0 + r) * 128 + c8);
        *(uint4*)(sm + SQL + off) = *(const uint4*)(Ql + (size_t)(i0 + r) * 128 + c8);
    }

    float O[4][4][4];   // [mt][dt][4]
    float lp[4][2];     // local row-sum partials [mt][half]
#pragma unroll
    for (int a = 0; a < 4; a++) {
        lp[a][0] = lp[a][1] = 0.f;
#pragma unroll
        for (int d = 0; d < 4; d++)
#pragma unroll
            for (int k = 0; k < 4; k++) O[a][d][k] = 0.f;
    }

    for (int t = 0; t < HW / BNT; t++) {
        const int j0 = t * BNT;
        // ---- load K tile [64][128] hi/lo ----
#pragma unroll 2
        for (int i = tid; i < 1024; i += 256) {
            int r = i >> 4, c8 = (i & 15) * 8;
            uint32_t off = off256(r, c8);
            *(uint4*)(sm + SKH + off) = *(const uint4*)(Kh + (size_t)(j0 + r) * 128 + c8);
            *(uint4*)(sm + SKL + off) = *(const uint4*)(Kl + (size_t)(j0 + r) * 128 + c8);
        }
        // ---- load V tile [128][64] hi/lo ----
#pragma unroll 2
        for (int i = tid; i < 1024; i += 256) {
            int d = i >> 3, j8 = (i & 7) * 8;
            uint32_t off = off128b(d, j8);
            *(uint4*)(sm + SVH + off) = *(const uint4*)(Vh + (size_t)d * HW + j0 + j8);
            *(uint4*)(sm + SVL + off) = *(const uint4*)(Vl + (size_t)d * HW + j0 + j8);
        }
        __syncthreads();

        // ---- S = Q K^T (bf16x3): warp computes m64 x n16 ----
        float S[4][2][4];
#pragma unroll
        for (int a = 0; a < 4; a++)
#pragma unroll
            for (int n = 0; n < 2; n++)
#pragma unroll
                for (int k = 0; k < 4; k++) S[a][n][k] = 0.f;

#pragma unroll
        for (int ks = 0; ks < 8; ks++) {
            const int c0 = ks * 16;
            uint32_t qfh[4][4], qfl[4][4], kfh[4], kfl[4];
#pragma unroll
            for (int mt = 0; mt < 4; mt++) {
                uint32_t off = off256(wm * 64 + mt * 16 + lr, c0 + lk);
                ldsm4(qfh[mt], smb + SQH + off);
                ldsm4(qfl[mt], smb + SQL + off);
            }
            {
                uint32_t off = off256(wn * 16 + lr, c0 + lk);
                ldsm4(kfh, smb + SKH + off);
                ldsm4(kfl, smb + SKL + off);
            }
#pragma unroll
            for (int mt = 0; mt < 4; mt++) {
                // n-tile 0 = {r0,r2}, n-tile 1 = {r1,r3}
                mma16816(S[mt][0], qfh[mt], kfh[0], kfh[2]);
                mma16816(S[mt][1], qfh[mt], kfh[1], kfh[3]);
                mma16816(S[mt][0], qfh[mt], kfl[0], kfl[2]);
                mma16816(S[mt][1], qfh[mt], kfl[1], kfl[3]);
                mma16816(S[mt][0], qfl[mt], kfh[0], kfh[2]);
                mma16816(S[mt][1], qfl[mt], kfh[1], kfh[3]);
            }
        }

        // ---- exp, accumulate row sums, pack P hi/lo to smem ----
#pragma unroll
        for (int mt = 0; mt < 4; mt++) {
#pragma unroll
            for (int nt = 0; nt < 2; nt++) {
                float e0 = __expf(S[mt][nt][0]);
                float e1 = __expf(S[mt][nt][1]);
                float e2 = __expf(S[mt][nt][2]);
                float e3 = __expf(S[mt][nt][3]);
                lp[mt][0] += e0 + e1;
                lp[mt][1] += e2 + e3;
                int col = wn * 16 + nt * 8 + qc;
                int row1 = wm * 64 + mt * 16 + qr, row2 = row1 + 8;  // FIX: wm*64
                uint32_t h0, l0, h1, l1;
                bfsplit2(e0, e1, h0, l0);
                bfsplit2(e2, e3, h1, l1);
                *(uint32_t*)(sm + SPH + off128b(row1, col)) = h0;
                *(uint32_t*)(sm + SPL + off128b(row1, col)) = l0;
                *(uint32_t*)(sm + SPH + off128b(row2, col)) = h1;
                *(uint32_t*)(sm + SPL + off128b(row2, col)) = l1;
            }
        }
        __syncthreads();

        // ---- O += P V (bf16x3): warp computes m64 x d32 ----
#pragma unroll
        for (int ks = 0; ks < 4; ks++) {
            const int j8 = ks * 16;
            uint32_t pfh[4][4], pfl[4][4], vfh[2][4], vfl[2][4];
#pragma unroll
            for (int mt = 0; mt < 4; mt++) {
                uint32_t off = off128b(wm * 64 + mt * 16 + lr, j8 + lk);
                ldsm4(pfh[mt], smb + SPH + off);
                ldsm4(pfl[mt], smb + SPL + off);
            }
#pragma unroll
            for (int vh = 0; vh < 2; vh++) {
                uint32_t off = off128b(wn * 32 + vh * 16 + lr, j8 + lk);
                ldsm4(vfh[vh], smb + SVH + off);
                ldsm4(vfl[vh], smb + SVL + off);
            }
#pragma unroll
            for (int mt = 0; mt < 4; mt++) {
#pragma unroll
                for (int vh = 0; vh < 2; vh++) {
                    mma16816(O[mt][2*vh+0], pfh[mt], vfh[vh][0], vfh[vh][2]);
                    mma16816(O[mt][2*vh+1], pfh[mt], vfh[vh][1], vfh[vh][3]);
                    mma16816(O[mt][2*vh+0], pfh[mt], vfl[vh][0], vfl[vh][2]);
                    mma16816(O[mt][2*vh+1], pfh[mt], vfl[vh][1], vfl[vh][3]);
                    mma16816(O[mt][2*vh+0], pfl[mt], vfh[vh][0], vfh[vh][2]);
                    mma16816(O[mt][2*vh+1], pfl[mt], vfh[vh][1], vfh[vh][3]);
                }
            }
        }
        __syncthreads();
    }

    // ---- combine row sums: quad reduce, write partials, cross-warp sum ----
#pragma unroll
    for (int mt = 0; mt < 4; mt++) {
#pragma unroll
        for (int h = 0; h < 2; h++) {
            float v = lp[mt][h];
            v += __shfl_xor_sync(0xffffffffu, v, 1);
            v += __shfl_xor_sync(0xffffffffu, v, 2);
            if ((lane & 3) == 0)
                *(float*)(sm + SLS + (wn * 128 + wm * 64 + mt * 16 + h * 8 + qr) * 4) = v;
        }
    }
    __syncthreads();

    // ---- epilogue: O / l -> g_res [i][d] ----
    float* R = g_res + bo;
#pragma unroll
    for (int mt = 0; mt < 4; mt++) {
        int r1 = wm * 64 + mt * 16 + qr, r2 = r1 + 8;
        float s1 = *(float*)(sm + SLS + r1 * 4) + *(float*)(sm + SLS + (128 + r1) * 4)
                 + *(float*)(sm + SLS + (256 + r1) * 4) + *(float*)(sm + SLS + (384 + r1) * 4);
        float s2 = *(float*)(sm + SLS + r2 * 4) + *(float*)(sm + SLS + (128 + r2) * 4)
                 + *(float*)(sm + SLS + (256 + r2) * 4) + *(float*)(sm + SLS + (384 + r2) * 4);
        float inv1 = 1.0f / s1, inv2 = 1.0f / s2;
#pragma unroll
        for (int dt = 0; dt < 4; dt++) {
            int d = wn * 32 + dt * 8 + qc;
            *(float2*)&R[(size_t)(i0 + r1) * 128 + d] =
                make_float2(O[mt][dt][0] * inv1, O[mt][dt][1] * inv1);
            *(float2*)&R[(size_t)(i0 + r2) * 128 + d] =
                make_float2(O[mt][dt][2] * inv2, O[mt][dt][3] * inv2);
        }
    }
}

// ---------------------------------------------------------------------------
// Kernel 3: out = BN(w4 @ res_view) + x  (FFMA2 128x128)
// ---------------------------------------------------------------------------
__global__ __launch_bounds__(256) void out_gemm_kernel(
        const float* __restrict__ x,
        const float* __restrict__ w4,
        const float* __restrict__ gamma,
        const float* __restrict__ beta,
        const float* __restrict__ rmean,
        const float* __restrict__ rvar,
        float* __restrict__ out) {
    const int b = blockIdx.z;
    const float* R = g_res + (size_t)b * CH * HW;
    const int o0 = blockIdx.y * 128, p0 = blockIdx.x * 128;

    __shared__ float Ws[32 * 132];
    __shared__ float Rs[32 * 132];

    const int tid = threadIdx.x;
    const int tx = tid & 15, ty = tid >> 4;
    const int r0 = ty * 8, pc = tx * 8;

    unsigned long long acc[4][8];
#pragma unroll
    for (int q = 0; q < 4; q++)
#pragma unroll
        for (int t = 0; t < 8; t++) acc[q][t] = 0ull;

    for (int c0 = 0; c0 < CH; c0 += 32) {
#pragma unroll
        for (int i = tid; i < 1024; i += 256) {
            int f = i >> 3, c4 = (i & 7) * 4;
            float4 wv = *(const float4*)&w4[(o0 + f) * CH + c0 + c4];
            Ws[(c4 + 0) * 132 + f] = wv.x;
            Ws[(c4 + 1) * 132 + f] = wv.y;
            Ws[(c4 + 2) * 132 + f] = wv.z;
            Ws[(c4 + 3) * 132 + f] = wv.w;
        }
#pragma unroll
        for (int i = tid; i < 1024; i += 256) {
            int c = i >> 5, p4 = (i & 31) * 4;
            *(float4*)&Rs[c * 132 + p4] = *(const float4*)&R[(size_t)(c0 + c) * HW + p0 + p4];
        }
        __syncthreads();
#pragma unroll
        for (int c = 0; c < 32; c++) {
            float4 wa = *(const float4*)&Ws[c * 132 + r0];
            float4 wb = *(const float4*)&Ws[c * 132 + r0 + 4];
            float4 ra = *(const float4*)&Rs[c * 132 + pc];
            float4 rb = *(const float4*)&Rs[c * 132 + pc + 4];
            unsigned long long wp[4] = {pk2(wa.x, wa.y), pk2(wa.z, wa.w),
                                        pk2(wb.x, wb.y), pk2(wb.z, wb.w)};
            float rr[8] = {ra.x, ra.y, ra.z, ra.w, rb.x, rb.y, rb.z, rb.w};
#pragma unroll
            for (int t = 0; t < 8; t++) {
                unsigned long long rbc = pk2(rr[t], rr[t]);
#pragma unroll
                for (int q = 0; q < 4; q++) ffma2(acc[q][t], wp[q], rbc);
            }
        }
        __syncthreads();
    }

#pragma unroll
    for (int q = 0; q < 4; q++) {
        float o0v[8], o1v[8];
#pragma unroll
        for (int t = 0; t < 8; t++) {
            float2 v = upk2(acc[q][t]);
            o0v[t] = v.x; o1v[t] = v.y;
        }
#pragma unroll
        for (int h = 0; h < 2; h++) {
            int oc = o0 + r0 + 2 * q + h;
            float sc = gamma[oc] * rsqrtf(rvar[oc] + 1e-5f);
            float mu = rmean[oc], bt = beta[oc];
            const float* vv = h ? o1v : o0v;
            size_t base = (size_t)b * CIN * HW + (size_t)oc * HW + p0 + pc;
            float4 xv0 = *(const float4*)&x[base];
            float4 xv1 = *(const float4*)&x[base + 4];
            float4 w0, w1;
            w0.x = (vv[0] - mu) * sc + bt + xv0.x;
            w0.y = (vv[1] - mu) * sc + bt + xv0.y;
            w0.z = (vv[2] - mu) * sc + bt + xv0.z;
            w0.w = (vv[3] - mu) * sc + bt + xv0.w;
            w1.x = (vv[4] - mu) * sc + bt + xv1.x;
            w1.y = (vv[5] - mu) * sc + bt + xv1.y;
            w1.z = (vv[6] - mu) * sc + bt + xv1.z;
            w1.w = (vv[7] - mu) * sc + bt + xv1.w;
            *(float4*)&out[base]     = w0;
            *(float4*)&out[base + 4] = w1;
        }
    }
}

// ---------------------------------------------------------------------------
extern "C" void kernel_launch(void* const* d_in, const int* in_sizes, int n_in,
                              void* d_out, int out_size) {
    const float* x     = (const float*)d_in[0];
    const float* w1    = (const float*)d_in[1];
    const float* w2    = (const float*)d_in[2];
    const float* w3    = (const float*)d_in[3];
    const float* w4    = (const float*)d_in[4];
    const float* gamma = (const float*)d_in[5];
    const float* beta  = (const float*)d_in[6];
    const float* rmean = (const float*)d_in[7];
    const float* rvar  = (const float*)d_in[8];
    float* out = (float*)d_out;

    qkv_gemm_kernel<<<dim3(32, 1, 12), 256>>>(x, w1, w2, w3);

    cudaFuncSetAttribute(flash_mma,
                         cudaFuncAttributeMaxDynamicSharedMemorySize, FLASH_SMEM);
    flash_mma<<<dim3(32, 4), 256, FLASH_SMEM>>>();

    out_gemm_kernel<<<dim3(32, 2, 4), 256>>>(x, w4, gamma, beta, rmean, rvar, out);
}

// round 7
// speedup vs baseline: 4.0005x; 1.6728x over previous
#include <cuda_runtime.h>
#include <cuda_bf16.h>
#include <cstdint>

#define HW   4096
#define CIN  256
#define CH   128
#define NB   4

// Scratch (__device__ globals; allocation-free rule). ALL natural [f][p] layouts.
__device__ __nv_bfloat16 g_qh[NB*CH*HW], g_ql[NB*CH*HW];  // Q viewed [i=4096][c=128]
__device__ __nv_bfloat16 g_kh[NB*CH*HW], g_kl[NB*CH*HW];  // K natural [c=128][j=4096]
__device__ __nv_bfloat16 g_vh[NB*CH*HW], g_vl[NB*CH*HW];  // V viewed [j=4096][d=128]
__device__ float g_res[NB*CH*HW];                          // res [i][d] flat = [128][4096] view

// ---- packed f32x2 helpers (FFMA2) ------------------------------------------
__device__ __forceinline__ unsigned long long pk2(float x, float y) {
    unsigned long long r;
    asm("mov.b64 %0, {%1, %2};" : "=l"(r) : "f"(x), "f"(y));
    return r;
}
__device__ __forceinline__ float2 upk2(unsigned long long v) {
    float2 r;
    asm("mov.b64 {%0, %1}, %2;" : "=f"(r.x), "=f"(r.y) : "l"(v));
    return r;
}
__device__ __forceinline__ void ffma2(unsigned long long& d,
                                      unsigned long long a,
                                      unsigned long long b) {
    asm("fma.rn.f32x2 %0, %1, %2, %0;" : "+l"(d) : "l"(a), "l"(b));
}

// ---- bf16 hi/lo split ------------------------------------------------------
__device__ __forceinline__ uint32_t b2u(__nv_bfloat162 v) {
    return *reinterpret_cast<uint32_t*>(&v);
}
__device__ __forceinline__ void bfsplit2(float a, float b,
                                         uint32_t& hi, uint32_t& lo) {
    __nv_bfloat162 h = __floats2bfloat162_rn(a, b);
    float ra = a - __low2float(h);
    float rb = b - __high2float(h);
    __nv_bfloat162 l = __floats2bfloat162_rn(ra, rb);
    hi = b2u(h); lo = b2u(l);
}

__device__ __forceinline__ uint32_t smem_u32(const void* p) {
    uint32_t a;
    asm("{ .reg .u64 t; cvta.to.shared.u64 t, %1; cvt.u32.u64 %0, t; }"
        : "=r"(a) : "l"(p));
    return a;
}

// ---- mma.sync / ldmatrix / cp.async wrappers (portable sm_80+) -------------
__device__ __forceinline__ void ldsm4(uint32_t* r, uint32_t addr) {
    asm volatile("ldmatrix.sync.aligned.m8n8.x4.shared.b16 {%0,%1,%2,%3}, [%4];"
                 : "=r"(r[0]), "=r"(r[1]), "=r"(r[2]), "=r"(r[3]) : "r"(addr));
}
__device__ __forceinline__ void ldsm4t(uint32_t* r, uint32_t addr) {
    asm volatile("ldmatrix.sync.aligned.m8n8.x4.trans.shared.b16 {%0,%1,%2,%3}, [%4];"
                 : "=r"(r[0]), "=r"(r[1]), "=r"(r[2]), "=r"(r[3]) : "r"(addr));
}
__device__ __forceinline__ void mma16816(float* d, const uint32_t* a,
                                         uint32_t b0, uint32_t b1) {
    asm volatile(
        "mma.sync.aligned.m16n8k16.row.col.f32.bf16.bf16.f32 "
        "{%0,%1,%2,%3}, {%4,%5,%6,%7}, {%8,%9}, {%0,%1,%2,%3};"
        : "+f"(d[0]), "+f"(d[1]), "+f"(d[2]), "+f"(d[3])
        : "r"(a[0]), "r"(a[1]), "r"(a[2]), "r"(a[3]), "r"(b0), "r"(b1));
}
__device__ __forceinline__ void cpasync16(uint32_t dst, const void* src) {
    asm volatile("cp.async.cg.shared.global [%0], [%1], 16;" :: "r"(dst), "l"(src));
}
#define CP_COMMIT() asm volatile("cp.async.commit_group;" ::: "memory")
#define CP_WAIT1()  asm volatile("cp.async.wait_group 1;" ::: "memory")
#define CP_WAIT0()  asm volatile("cp.async.wait_group 0;" ::: "memory")

// ---- swizzled smem offsets (16B chunk XOR by row) --------------------------
__device__ __forceinline__ uint32_t off256(int r, int c) {  // 256B rows, 128 bf16 cols
    return (uint32_t)(r * 256 + ((((c >> 3) ^ r) & 7) << 4) + ((c >> 3) & ~7) * 16 + (c & 7) * 2);
}
__device__ __forceinline__ uint32_t off128b(int r, int c) { // 128B rows, 64 bf16 cols
    return (uint32_t)(r * 128 + (((c >> 3) ^ (r & 7)) << 4) + (c & 7) * 2);
}

// flash smem layout (bytes)
#define SQH 0
#define SQL 32768
#define SST 65536          // K/V stages start
#define KHO 0
#define KLO 16384
#define VHO 32768
#define VLO 49152
#define STAGE 65536
#define FLASH_SMEM (SST + 2 * STAGE)   // 192 KB

// ---------------------------------------------------------------------------
// Kernel 1: QKV projections (FFMA2). Epilogue identical for all three:
// coalesced bf16 hi/lo stores in the NATURAL [f][p] layout.
// ---------------------------------------------------------------------------
__global__ __launch_bounds__(256) void qkv_gemm_kernel(
        const float* __restrict__ x,
        const float* __restrict__ w1,
        const float* __restrict__ w2,
        const float* __restrict__ w3) {
    const int b = blockIdx.z / 3, s = blockIdx.z % 3;
    const float* W = (s == 0) ? w1 : (s == 1) ? w2 : w3;
    const float* X = x + (size_t)b * CIN * HW;
    const int p0 = blockIdx.x * 128;
    const size_t bo = (size_t)b * CH * HW;

    __shared__ float Ws[32 * 132];
    __shared__ float Xs[32 * 132];

    const int tid = threadIdx.x;
    const int tx = tid & 15, ty = tid >> 4;
    const int r0 = ty * 8, pc = tx * 8;

    unsigned long long acc[4][8];
#pragma unroll
    for (int q = 0; q < 4; q++)
#pragma unroll
        for (int t = 0; t < 8; t++) acc[q][t] = 0ull;

    for (int c0 = 0; c0 < CIN; c0 += 32) {
#pragma unroll
        for (int i = tid; i < 1024; i += 256) {
            int f = i >> 3, c4 = (i & 7) * 4;
            float4 wv = *(const float4*)&W[f * CIN + c0 + c4];
            Ws[(c4 + 0) * 132 + f] = wv.x;
            Ws[(c4 + 1) * 132 + f] = wv.y;
            Ws[(c4 + 2) * 132 + f] = wv.z;
            Ws[(c4 + 3) * 132 + f] = wv.w;
        }
#pragma unroll
        for (int i = tid; i < 1024; i += 256) {
            int c = i >> 5, p4 = (i & 31) * 4;
            *(float4*)&Xs[c * 132 + p4] = *(const float4*)&X[(size_t)(c0 + c) * HW + p0 + p4];
        }
        __syncthreads();
#pragma unroll
        for (int c = 0; c < 32; c++) {
            float4 wa = *(const float4*)&Ws[c * 132 + r0];
            float4 wb = *(const float4*)&Ws[c * 132 + r0 + 4];
            float4 xa = *(const float4*)&Xs[c * 132 + pc];
            float4 xb = *(const float4*)&Xs[c * 132 + pc + 4];
            unsigned long long wp[4] = {pk2(wa.x, wa.y), pk2(wa.z, wa.w),
                                        pk2(wb.x, wb.y), pk2(wb.z, wb.w)};
            float xr[8] = {xa.x, xa.y, xa.z, xa.w, xb.x, xb.y, xb.z, xb.w};
#pragma unroll
            for (int t = 0; t < 8; t++) {
                unsigned long long xbc = pk2(xr[t], xr[t]);
#pragma unroll
                for (int q = 0; q < 4; q++) ffma2(acc[q][t], wp[q], xbc);
            }
        }
        __syncthreads();
    }

    __nv_bfloat16* OH = ((s == 0) ? g_qh : (s == 1) ? g_kh : g_vh) + bo;
    __nv_bfloat16* OL = ((s == 0) ? g_ql : (s == 1) ? g_kl : g_vl) + bo;
#pragma unroll
    for (int q = 0; q < 4; q++) {
        float o0[8], o1[8];
#pragma unroll
        for (int t = 0; t < 8; t++) {
            float2 v = upk2(acc[q][t]);
            o0[t] = v.x; o1[t] = v.y;
        }
#pragma unroll
        for (int h = 0; h < 2; h++) {
            const float* vv = h ? o1 : o0;
            int f = r0 + 2 * q + h;
            uint32_t hh[4], ll[4];
#pragma unroll
            for (int u = 0; u < 4; u++) bfsplit2(vv[2*u], vv[2*u+1], hh[u], ll[u]);
            *(uint4*)&OH[(size_t)f * HW + p0 + pc] = *(uint4*)hh;
            *(uint4*)&OL[(size_t)f * HW + p0 + pc] = *(uint4*)ll;
        }
    }
}

// ---------------------------------------------------------------------------
// Kernel 2: FA2-style flash attention, mma.sync bf16x3, no-max softmax,
// in-register P, cp.async double-buffered K/V tiles.
// 8 warps, each owns m16 x full-width. BM=128, BN=64, D=128.
// ---------------------------------------------------------------------------
__global__ __launch_bounds__(256, 1) void flash_mma() {
    extern __shared__ char sm[];
    const uint32_t smb = smem_u32(sm);
    const int tid = threadIdx.x, lane = tid & 31, wid = tid >> 5;
    const int lr = lane & 15, lk = (lane >> 4) * 8;
    const int m0 = wid * 16;
    const int b = blockIdx.y, i0 = blockIdx.x * 128;
    const size_t bo = (size_t)b * CH * HW;
    const __nv_bfloat16 *Qh = g_qh + bo, *Ql = g_ql + bo;
    const __nv_bfloat16 *Kh = g_kh + bo, *Kl = g_kl + bo;
    const __nv_bfloat16 *Vh = g_vh + bo, *Vl = g_vl + bo;

    // ---- persistent Q tile ----
#pragma unroll 4
    for (int i = tid; i < 2048; i += 256) {
        int r = i >> 4, c8 = (i & 15) * 8;
        uint32_t off = off256(r, c8);
        *(uint4*)(sm + SQH + off) = *(const uint4*)(Qh + (size_t)(i0 + r) * 128 + c8);
        *(uint4*)(sm + SQL + off) = *(const uint4*)(Ql + (size_t)(i0 + r) * 128 + c8);
    }

    // ---- tile prefetch helper (16 cp.async / thread) ----
    auto prefetch = [&](int tt, int stg) {
        const int j0 = tt * 64;
        const uint32_t base = smb + SST + (uint32_t)stg * STAGE;
#pragma unroll
        for (int q = 0; q < 4; q++) {
            int i = tid + q * 256;
            {   // K: [c=128][j=64] tile from natural [c][j_global]
                int c = i >> 3, j8 = (i & 7) * 8;
                uint32_t o = off128b(c, j8);
                cpasync16(base + KHO + o, Kh + (size_t)c * HW + j0 + j8);
                cpasync16(base + KLO + o, Kl + (size_t)c * HW + j0 + j8);
            }
            {   // V: [j=64][d=128] tile from natural [j][d]
                int j = i >> 4, d8 = (i & 15) * 8;
                uint32_t o = off256(j, d8);
                cpasync16(base + VHO + o, Vh + (size_t)(j0 + j) * 128 + d8);
                cpasync16(base + VLO + o, Vl + (size_t)(j0 + j) * 128 + d8);
            }
        }
    };

    prefetch(0, 0);
    CP_COMMIT();

    float O[16][4];
#pragma unroll
    for (int d = 0; d < 16; d++)
#pragma unroll
        for (int k = 0; k < 4; k++) O[d][k] = 0.f;
    float ls0 = 0.f, ls1 = 0.f;

    for (int t = 0; t < 64; t++) {
        if (t < 63) { prefetch(t + 1, (t + 1) & 1); CP_COMMIT(); CP_WAIT1(); }
        else        { CP_WAIT0(); }
        __syncthreads();
        const uint32_t kb = smb + SST + (uint32_t)(t & 1) * STAGE;

        // ---- S = Q K^T (bf16x3): warp computes m16 x n64 ----
        float S[8][4];
#pragma unroll
        for (int n = 0; n < 8; n++)
#pragma unroll
            for (int k = 0; k < 4; k++) S[n][k] = 0.f;

#pragma unroll
        for (int ks = 0; ks < 8; ks++) {
            uint32_t qh[4], ql[4];
            uint32_t qoff = off256(m0 + lr, ks * 16 + lk);
            ldsm4(qh, smb + SQH + qoff);
            ldsm4(ql, smb + SQL + qoff);
#pragma unroll
            for (int jg = 0; jg < 4; jg++) {
                uint32_t khf[4], klf[4];
                uint32_t koff = off128b(ks * 16 + lr, jg * 16 + lk);
                ldsm4t(khf, kb + KHO + koff);
                ldsm4t(klf, kb + KLO + koff);
                mma16816(S[jg*2],   qh, khf[0], khf[1]);
                mma16816(S[jg*2+1], qh, khf[2], khf[3]);
                mma16816(S[jg*2],   qh, klf[0], klf[1]);
                mma16816(S[jg*2+1], qh, klf[2], klf[3]);
                mma16816(S[jg*2],   ql, khf[0], khf[1]);
                mma16816(S[jg*2+1], ql, khf[2], khf[3]);
            }
        }

        // ---- exp + in-register P pack (FA2 accum->A-frag) + row sums ----
        uint32_t pH[4][4], pL[4][4];
        float a0 = 0.f, a1 = 0.f;
#pragma unroll
        for (int nb = 0; nb < 8; nb++) {
            float e0 = __expf(S[nb][0]), e1 = __expf(S[nb][1]);
            float e2 = __expf(S[nb][2]), e3 = __expf(S[nb][3]);
            a0 += e0 + e1; a1 += e2 + e3;
            int kbi = nb >> 1, hf = (nb & 1) * 2;
            bfsplit2(e0, e1, pH[kbi][hf],     pL[kbi][hf]);
            bfsplit2(e2, e3, pH[kbi][hf + 1], pL[kbi][hf + 1]);
        }
        a0 += __shfl_xor_sync(0xffffffffu, a0, 1);
        a0 += __shfl_xor_sync(0xffffffffu, a0, 2);
        a1 += __shfl_xor_sync(0xffffffffu, a1, 1);
        a1 += __shfl_xor_sync(0xffffffffu, a1, 2);
        ls0 += a0; ls1 += a1;

        // ---- O += P V (bf16x3): warp computes m16 x d128 ----
#pragma unroll
        for (int kbi = 0; kbi < 4; kbi++) {
#pragma unroll
            for (int dg = 0; dg < 8; dg++) {
                uint32_t vhf[4], vlf[4];
                uint32_t voff = off256(kbi * 16 + lr, dg * 16 + lk);
                ldsm4t(vhf, kb + VHO + voff);
                ldsm4t(vlf, kb + VLO + voff);
                mma16816(O[dg*2],   pH[kbi], vhf[0], vhf[1]);
                mma16816(O[dg*2+1], pH[kbi], vhf[2], vhf[3]);
                mma16816(O[dg*2],   pH[kbi], vlf[0], vlf[1]);
                mma16816(O[dg*2+1], pH[kbi], vlf[2], vlf[3]);
                mma16816(O[dg*2],   pL[kbi], vhf[0], vhf[1]);
                mma16816(O[dg*2+1], pL[kbi], vhf[2], vhf[3]);
            }
        }
        __syncthreads();   // all warps done reading stage (t&1) before overwrite
    }

    // ---- epilogue: O / l -> g_res [i][d] ----
    float inv0 = 1.0f / ls0, inv1 = 1.0f / ls1;
    int r1 = i0 + m0 + (lane >> 2), r2 = r1 + 8;
    float* R = g_res + bo;
#pragma unroll
    for (int db = 0; db < 16; db++) {
        int d = db * 8 + (lane & 3) * 2;
        *(float2*)&R[(size_t)r1 * 128 + d] = make_float2(O[db][0] * inv0, O[db][1] * inv0);
        *(float2*)&R[(size_t)r2 * 128 + d] = make_float2(O[db][2] * inv1, O[db][3] * inv1);
    }
}

// ---------------------------------------------------------------------------
// Kernel 3: out = BN(w4 @ res_view) + x  (FFMA2 128x128)
// ---------------------------------------------------------------------------
__global__ __launch_bounds__(256) void out_gemm_kernel(
        const float* __restrict__ x,
        const float* __restrict__ w4,
        const float* __restrict__ gamma,
        const float* __restrict__ beta,
        const float* __restrict__ rmean,
        const float* __restrict__ rvar,
        float* __restrict__ out) {
    const int b = blockIdx.z;
    const float* R = g_res + (size_t)b * CH * HW;
    const int o0 = blockIdx.y * 128, p0 = blockIdx.x * 128;

    __shared__ float Ws[32 * 132];
    __shared__ float Rs[32 * 132];

    const int tid = threadIdx.x;
    const int tx = tid & 15, ty = tid >> 4;
    const int r0 = ty * 8, pc = tx * 8;

    unsigned long long acc[4][8];
#pragma unroll
    for (int q = 0; q < 4; q++)
#pragma unroll
        for (int t = 0; t < 8; t++) acc[q][t] = 0ull;

    for (int c0 = 0; c0 < CH; c0 += 32) {
#pragma unroll
        for (int i = tid; i < 1024; i += 256) {
            int f = i >> 3, c4 = (i & 7) * 4;
            float4 wv = *(const float4*)&w4[(o0 + f) * CH + c0 + c4];
            Ws[(c4 + 0) * 132 + f] = wv.x;
            Ws[(c4 + 1) * 132 + f] = wv.y;
            Ws[(c4 + 2) * 132 + f] = wv.z;
            Ws[(c4 + 3) * 132 + f] = wv.w;
        }
#pragma unroll
        for (int i = tid; i < 1024; i += 256) {
            int c = i >> 5, p4 = (i & 31) * 4;
            *(float4*)&Rs[c * 132 + p4] = *(const float4*)&R[(size_t)(c0 + c) * HW + p0 + p4];
        }
        __syncthreads();
#pragma unroll
        for (int c = 0; c < 32; c++) {
            float4 wa = *(const float4*)&Ws[c * 132 + r0];
            float4 wb = *(const float4*)&Ws[c * 132 + r0 + 4];
            float4 ra = *(const float4*)&Rs[c * 132 + pc];
            float4 rb = *(const float4*)&Rs[c * 132 + pc + 4];
            unsigned long long wp[4] = {pk2(wa.x, wa.y), pk2(wa.z, wa.w),
                                        pk2(wb.x, wb.y), pk2(wb.z, wb.w)};
            float rr[8] = {ra.x, ra.y, ra.z, ra.w, rb.x, rb.y, rb.z, rb.w};
#pragma unroll
            for (int t = 0; t < 8; t++) {
                unsigned long long rbc = pk2(rr[t], rr[t]);
#pragma unroll
                for (int q = 0; q < 4; q++) ffma2(acc[q][t], wp[q], rbc);
            }
        }
        __syncthreads();
    }

#pragma unroll
    for (int q = 0; q < 4; q++) {
        float o0v[8], o1v[8];
#pragma unroll
        for (int t = 0; t < 8; t++) {
            float2 v = upk2(acc[q][t]);
            o0v[t] = v.x; o1v[t] = v.y;
        }
#pragma unroll
        for (int h = 0; h < 2; h++) {
            int oc = o0 + r0 + 2 * q + h;
            float sc = gamma[oc] * rsqrtf(rvar[oc] + 1e-5f);
            float mu = rmean[oc], bt = beta[oc];
            const float* vv = h ? o1v : o0v;
            size_t base = (size_t)b * CIN * HW + (size_t)oc * HW + p0 + pc;
            float4 xv0 = *(const float4*)&x[base];
            float4 xv1 = *(const float4*)&x[base + 4];
            float4 w0, w1;
            w0.x = (vv[0] - mu) * sc + bt + xv0.x;
            w0.y = (vv[1] - mu) * sc + bt + xv0.y;
            w0.z = (vv[2] - mu) * sc + bt + xv0.z;
            w0.w = (vv[3] - mu) * sc + bt + xv0.w;
            w1.x = (vv[4] - mu) * sc + bt + xv1.x;
            w1.y = (vv[5] - mu) * sc + bt + xv1.y;
            w1.z = (vv[6] - mu) * sc + bt + xv1.z;
            w1.w = (vv[7] - mu) * sc + bt + xv1.w;
            *(float4*)&out[base]     = w0;
            *(float4*)&out[base + 4] = w1;
        }
    }
}

// ---------------------------------------------------------------------------
extern "C" void kernel_launch(void* const* d_in, const int* in_sizes, int n_in,
                              void* d_out, int out_size) {
    const float* x     = (const float*)d_in[0];
    const float* w1    = (const float*)d_in[1];
    const float* w2    = (const float*)d_in[2];
    const float* w3    = (const float*)d_in[3];
    const float* w4    = (const float*)d_in[4];
    const float* gamma = (const float*)d_in[5];
    const float* beta  = (const float*)d_in[6];
    const float* rmean = (const float*)d_in[7];
    const float* rvar  = (const float*)d_in[8];
    float* out = (float*)d_out;

    qkv_gemm_kernel<<<dim3(32, 1, 12), 256>>>(x, w1, w2, w3);

    cudaFuncSetAttribute(flash_mma,
                         cudaFuncAttributeMaxDynamicSharedMemorySize, FLASH_SMEM);
    flash_mma<<<dim3(32, 4), 256, FLASH_SMEM>>>();

    out_gemm_kernel<<<dim3(32, 2, 4), 256>>>(x, w4, gamma, beta, rmean, rvar, out);
}

// round 8
// speedup vs baseline: 4.7646x; 1.1910x over previous
#include <cuda_runtime.h>
#include <cuda_bf16.h>
#include <cstdint>

#define HW   4096
#define CIN  256
#define CH   128
#define NB   4

// Scratch (__device__ globals; allocation-free rule). ALL natural [f][p] layouts.
__device__ __nv_bfloat16 g_qh[NB*CH*HW], g_ql[NB*CH*HW];  // Q viewed [i=4096][c=128]
__device__ __nv_bfloat16 g_kh[NB*CH*HW], g_kl[NB*CH*HW];  // K natural [c=128][j=4096]
__device__ __nv_bfloat16 g_vh[NB*CH*HW], g_vl[NB*CH*HW];  // V viewed [j=4096][d=128]
__device__ float g_res[NB*CH*HW];                          // res [i][d] flat = [128][4096] view

// ---- bf16 hi/lo split ------------------------------------------------------
__device__ __forceinline__ uint32_t b2u(__nv_bfloat162 v) {
    return *reinterpret_cast<uint32_t*>(&v);
}
__device__ __forceinline__ void bfsplit2(float a, float b,
                                         uint32_t& hi, uint32_t& lo) {
    __nv_bfloat162 h = __floats2bfloat162_rn(a, b);
    float ra = a - __low2float(h);
    float rb = b - __high2float(h);
    __nv_bfloat162 l = __floats2bfloat162_rn(ra, rb);
    hi = b2u(h); lo = b2u(l);
}

__device__ __forceinline__ uint32_t smem_u32(const void* p) {
    uint32_t a;
    asm("{ .reg .u64 t; cvta.to.shared.u64 t, %1; cvt.u32.u64 %0, t; }"
        : "=r"(a) : "l"(p));
    return a;
}

// ---- mma.sync / ldmatrix / cp.async wrappers (portable sm_80+) -------------
__device__ __forceinline__ void ldsm4(uint32_t* r, uint32_t addr) {
    asm volatile("ldmatrix.sync.aligned.m8n8.x4.shared.b16 {%0,%1,%2,%3}, [%4];"
                 : "=r"(r[0]), "=r"(r[1]), "=r"(r[2]), "=r"(r[3]) : "r"(addr));
}
__device__ __forceinline__ void ldsm4t(uint32_t* r, uint32_t addr) {
    asm volatile("ldmatrix.sync.aligned.m8n8.x4.trans.shared.b16 {%0,%1,%2,%3}, [%4];"
                 : "=r"(r[0]), "=r"(r[1]), "=r"(r[2]), "=r"(r[3]) : "r"(addr));
}
__device__ __forceinline__ void mma16816(float* d, const uint32_t* a,
                                         uint32_t b0, uint32_t b1) {
    asm volatile(
        "mma.sync.aligned.m16n8k16.row.col.f32.bf16.bf16.f32 "
        "{%0,%1,%2,%3}, {%4,%5,%6,%7}, {%8,%9}, {%0,%1,%2,%3};"
        : "+f"(d[0]), "+f"(d[1]), "+f"(d[2]), "+f"(d[3])
        : "r"(a[0]), "r"(a[1]), "r"(a[2]), "r"(a[3]), "r"(b0), "r"(b1));
}
__device__ __forceinline__ void cpasync16(uint32_t dst, const void* src) {
    asm volatile("cp.async.cg.shared.global [%0], [%1], 16;" :: "r"(dst), "l"(src));
}
#define CP_COMMIT() asm volatile("cp.async.commit_group;" ::: "memory")
#define CP_WAIT1()  asm volatile("cp.async.wait_group 1;" ::: "memory")
#define CP_WAIT0()  asm volatile("cp.async.wait_group 0;" ::: "memory")

// ---- swizzled smem offsets (16B chunk XOR by row) --------------------------
__device__ __forceinline__ uint32_t off256(int r, int c) {  // 256B rows, 128 bf16 cols
    return (uint32_t)(r * 256 + ((((c >> 3) ^ r) & 7) << 4) + ((c >> 3) & ~7) * 16 + (c & 7) * 2);
}
__device__ __forceinline__ uint32_t off128b(int r, int c) { // 128B rows, 64 bf16 cols
    return (uint32_t)(r * 128 + (((c >> 3) ^ (r & 7)) << 4) + (c & 7) * 2);
}

// ---------------------------------------------------------------------------
// Kernel 1: QKV projections via mma.sync bf16x3.
// CTA = (p-tile 128, batch). Splits X tile once, loops s in {w1,w2,w3}.
// ---------------------------------------------------------------------------
#define QS_XH 0            // X: [256 k][128 n] bf16, 256B rows
#define QS_XL 65536
#define QS_WH 131072       // W half: [128 m][128 k] bf16, 256B rows
#define QS_WL 163840
#define QKV_SMEM 196608    // 192 KB

__global__ __launch_bounds__(256, 1) void qkv_mma(
        const float* __restrict__ x,
        const float* __restrict__ w1,
        const float* __restrict__ w2,
        const float* __restrict__ w3) {
    extern __shared__ char sm[];
    const uint32_t smb = smem_u32(sm);
    const int tid = threadIdx.x, lane = tid & 31, wid = tid >> 5;
    const int lr = lane & 15, lk = (lane >> 4) * 8;
    const int qr = lane >> 2, qc = (lane & 3) * 2;
    const int m0 = wid * 16;
    const int b = blockIdx.y, p0 = blockIdx.x * 128;
    const float* X = x + (size_t)b * CIN * HW;
    const size_t bo = (size_t)b * CH * HW;

    // ---- split X tile [256][128] fp32 -> bf16 hi/lo smem (once) ----
#pragma unroll 4
    for (int i = tid; i < 256 * 32; i += 256) {
        int r = i >> 5, c4 = (i & 31) * 4;
        float4 v = *(const float4*)&X[(size_t)r * HW + p0 + c4];
        uint32_t h0, l0, h1, l1;
        bfsplit2(v.x, v.y, h0, l0);
        bfsplit2(v.z, v.w, h1, l1);
        uint32_t o = off256(r, c4);
        *(uint32_t*)(sm + QS_XH + o) = h0;
        *(uint32_t*)(sm + QS_XL + o) = l0;
        *(uint32_t*)(sm + QS_XH + o + 4) = h1;
        *(uint32_t*)(sm + QS_XL + o + 4) = l1;
    }
    __syncthreads();

#pragma unroll 1
    for (int s = 0; s < 3; s++) {
        const float* W = (s == 0) ? w1 : (s == 1) ? w2 : w3;
        __nv_bfloat16* OH = ((s == 0) ? g_qh : (s == 1) ? g_kh : g_vh) + bo;
        __nv_bfloat16* OL = ((s == 0) ? g_ql : (s == 1) ? g_kl : g_vl) + bo;

        float acc[16][4];
#pragma unroll
        for (int n = 0; n < 16; n++)
#pragma unroll
            for (int k = 0; k < 4; k++) acc[n][k] = 0.f;

#pragma unroll 1
        for (int kh = 0; kh < 2; kh++) {
            __syncthreads();   // previous mma done reading W smem
            // split W half [128 m][128 k]
#pragma unroll 4
            for (int i = tid; i < 128 * 32; i += 256) {
                int f = i >> 5, c4 = (i & 31) * 4;
                float4 v = *(const float4*)&W[f * CIN + kh * 128 + c4];
                uint32_t h0, l0, h1, l1;
                bfsplit2(v.x, v.y, h0, l0);
                bfsplit2(v.z, v.w, h1, l1);
                uint32_t o = off256(f, c4);
                *(uint32_t*)(sm + QS_WH + o) = h0;
                *(uint32_t*)(sm + QS_WL + o) = l0;
                *(uint32_t*)(sm + QS_WH + o + 4) = h1;
                *(uint32_t*)(sm + QS_WL + o + 4) = l1;
            }
            __syncthreads();

#pragma unroll
            for (int ks = 0; ks < 8; ks++) {
                uint32_t ah[4], al[4];
                uint32_t aoff = off256(m0 + lr, ks * 16 + lk);
                ldsm4(ah, smb + QS_WH + aoff);
                ldsm4(al, smb + QS_WL + aoff);
#pragma unroll
                for (int jg = 0; jg < 8; jg++) {
                    uint32_t bh[4], bl[4];
                    uint32_t boff = off256(kh * 128 + ks * 16 + lr, jg * 16 + lk);
                    ldsm4t(bh, smb + QS_XH + boff);
                    ldsm4t(bl, smb + QS_XL + boff);
                    mma16816(acc[jg*2],   ah, bh[0], bh[1]);
                    mma16816(acc[jg*2+1], ah, bh[2], bh[3]);
                    mma16816(acc[jg*2],   ah, bl[0], bl[1]);
                    mma16816(acc[jg*2+1], ah, bl[2], bl[3]);
                    mma16816(acc[jg*2],   al, bh[0], bh[1]);
                    mma16816(acc[jg*2+1], al, bh[2], bh[3]);
                }
            }
        }

        // ---- epilogue: split accum -> bf16 hi/lo, natural [f][p] ----
        int f1 = m0 + qr;
#pragma unroll
        for (int nb = 0; nb < 16; nb++) {
            int col = p0 + nb * 8 + qc;
            uint32_t h0, l0, h1, l1;
            bfsplit2(acc[nb][0], acc[nb][1], h0, l0);
            bfsplit2(acc[nb][2], acc[nb][3], h1, l1);
            *(uint32_t*)&OH[(size_t)f1 * HW + col] = h0;
            *(uint32_t*)&OL[(size_t)f1 * HW + col] = l0;
            *(uint32_t*)&OH[(size_t)(f1 + 8) * HW + col] = h1;
            *(uint32_t*)&OL[(size_t)(f1 + 8) * HW + col] = l1;
        }
    }
}

// ---------------------------------------------------------------------------
// Kernel 2: FA2-style flash attention (UNCHANGED from passing round 7).
// ---------------------------------------------------------------------------
#define SQH 0
#define SQL 32768
#define SST 65536
#define KHO 0
#define KLO 16384
#define VHO 32768
#define VLO 49152
#define STAGE 65536
#define FLASH_SMEM (SST + 2 * STAGE)   // 192 KB

__global__ __launch_bounds__(256, 1) void flash_mma() {
    extern __shared__ char sm[];
    const uint32_t smb = smem_u32(sm);
    const int tid = threadIdx.x, lane = tid & 31, wid = tid >> 5;
    const int lr = lane & 15, lk = (lane >> 4) * 8;
    const int m0 = wid * 16;
    const int b = blockIdx.y, i0 = blockIdx.x * 128;
    const size_t bo = (size_t)b * CH * HW;
    const __nv_bfloat16 *Qh = g_qh + bo, *Ql = g_ql + bo;
    const __nv_bfloat16 *Kh = g_kh + bo, *Kl = g_kl + bo;
    const __nv_bfloat16 *Vh = g_vh + bo, *Vl = g_vl + bo;

#pragma unroll 4
    for (int i = tid; i < 2048; i += 256) {
        int r = i >> 4, c8 = (i & 15) * 8;
        uint32_t off = off256(r, c8);
        *(uint4*)(sm + SQH + off) = *(const uint4*)(Qh + (size_t)(i0 + r) * 128 + c8);
        *(uint4*)(sm + SQL + off) = *(const uint4*)(Ql + (size_t)(i0 + r) * 128 + c8);
    }

    auto prefetch = [&](int tt, int stg) {
        const int j0 = tt * 64;
        const uint32_t base = smb + SST + (uint32_t)stg * STAGE;
#pragma unroll
        for (int q = 0; q < 4; q++) {
            int i = tid + q * 256;
            {
                int c = i >> 3, j8 = (i & 7) * 8;
                uint32_t o = off128b(c, j8);
                cpasync16(base + KHO + o, Kh + (size_t)c * HW + j0 + j8);
                cpasync16(base + KLO + o, Kl + (size_t)c * HW + j0 + j8);
            }
            {
                int j = i >> 4, d8 = (i & 15) * 8;
                uint32_t o = off256(j, d8);
                cpasync16(base + VHO + o, Vh + (size_t)(j0 + j) * 128 + d8);
                cpasync16(base + VLO + o, Vl + (size_t)(j0 + j) * 128 + d8);
            }
        }
    };

    prefetch(0, 0);
    CP_COMMIT();

    float O[16][4];
#pragma unroll
    for (int d = 0; d < 16; d++)
#pragma unroll
        for (int k = 0; k < 4; k++) O[d][k] = 0.f;
    float ls0 = 0.f, ls1 = 0.f;

    for (int t = 0; t < 64; t++) {
        if (t < 63) { prefetch(t + 1, (t + 1) & 1); CP_COMMIT(); CP_WAIT1(); }
        else        { CP_WAIT0(); }
        __syncthreads();
        const uint32_t kb = smb + SST + (uint32_t)(t & 1) * STAGE;

        float S[8][4];
#pragma unroll
        for (int n = 0; n < 8; n++)
#pragma unroll
            for (int k = 0; k < 4; k++) S[n][k] = 0.f;

#pragma unroll
        for (int ks = 0; ks < 8; ks++) {
            uint32_t qh[4], ql[4];
            uint32_t qoff = off256(m0 + lr, ks * 16 + lk);
            ldsm4(qh, smb + SQH + qoff);
            ldsm4(ql, smb + SQL + qoff);
#pragma unroll
            for (int jg = 0; jg < 4; jg++) {
                uint32_t khf[4], klf[4];
                uint32_t koff = off128b(ks * 16 + lr, jg * 16 + lk);
                ldsm4t(khf, kb + KHO + koff);
                ldsm4t(klf, kb + KLO + koff);
                mma16816(S[jg*2],   qh, khf[0], khf[1]);
                mma16816(S[jg*2+1], qh, khf[2], khf[3]);
                mma16816(S[jg*2],   qh, klf[0], klf[1]);
                mma16816(S[jg*2+1], qh, klf[2], klf[3]);
                mma16816(S[jg*2],   ql, khf[0], khf[1]);
                mma16816(S[jg*2+1], ql, khf[2], khf[3]);
            }
        }

        uint32_t pH[4][4], pL[4][4];
        float a0 = 0.f, a1 = 0.f;
#pragma unroll
        for (int nb = 0; nb < 8; nb++) {
            float e0 = __expf(S[nb][0]), e1 = __expf(S[nb][1]);
            float e2 = __expf(S[nb][2]), e3 = __expf(S[nb][3]);
            a0 += e0 + e1; a1 += e2 + e3;
            int kbi = nb >> 1, hf = (nb & 1) * 2;
            bfsplit2(e0, e1, pH[kbi][hf],     pL[kbi][hf]);
            bfsplit2(e2, e3, pH[kbi][hf + 1], pL[kbi][hf + 1]);
        }
        a0 += __shfl_xor_sync(0xffffffffu, a0, 1);
        a0 += __shfl_xor_sync(0xffffffffu, a0, 2);
        a1 += __shfl_xor_sync(0xffffffffu, a1, 1);
        a1 += __shfl_xor_sync(0xffffffffu, a1, 2);
        ls0 += a0; ls1 += a1;

#pragma unroll
        for (int kbi = 0; kbi < 4; kbi++) {
#pragma unroll
            for (int dg = 0; dg < 8; dg++) {
                uint32_t vhf[4], vlf[4];
                uint32_t voff = off256(kbi * 16 + lr, dg * 16 + lk);
                ldsm4t(vhf, kb + VHO + voff);
                ldsm4t(vlf, kb + VLO + voff);
                mma16816(O[dg*2],   pH[kbi], vhf[0], vhf[1]);
                mma16816(O[dg*2+1], pH[kbi], vhf[2], vhf[3]);
                mma16816(O[dg*2],   pH[kbi], vlf[0], vlf[1]);
                mma16816(O[dg*2+1], pH[kbi], vlf[2], vlf[3]);
                mma16816(O[dg*2],   pL[kbi], vhf[0], vhf[1]);
                mma16816(O[dg*2+1], pL[kbi], vhf[2], vhf[3]);
            }
        }
        __syncthreads();
    }

    float inv0 = 1.0f / ls0, inv1 = 1.0f / ls1;
    int r1 = i0 + m0 + (lane >> 2), r2 = r1 + 8;
    float* R = g_res + bo;
#pragma unroll
    for (int db = 0; db < 16; db++) {
        int d = db * 8 + (lane & 3) * 2;
        *(float2*)&R[(size_t)r1 * 128 + d] = make_float2(O[db][0] * inv0, O[db][1] * inv0);
        *(float2*)&R[(size_t)r2 * 128 + d] = make_float2(O[db][2] * inv1, O[db][3] * inv1);
    }
}

// ---------------------------------------------------------------------------
// Kernel 3: out = BN(w4 @ res_view) + x via mma.sync bf16x3.
// CTA = (p-tile 128, batch), loops the two o-halves. res_view = [c=128][p=4096].
// ---------------------------------------------------------------------------
#define OS_RH 0            // res: [128 c][128 p] bf16
#define OS_RL 32768
#define OS_WH 65536        // w4: [256 o][128 c] bf16
#define OS_WL 131072
#define OUT_SMEM 196608    // 192 KB

__global__ __launch_bounds__(256, 1) void out_mma(
        const float* __restrict__ x,
        const float* __restrict__ w4,
        const float* __restrict__ gamma,
        const float* __restrict__ beta,
        const float* __restrict__ rmean,
        const float* __restrict__ rvar,
        float* __restrict__ out) {
    extern __shared__ char sm[];
    const uint32_t smb = smem_u32(sm);
    const int tid = threadIdx.x, lane = tid & 31, wid = tid >> 5;
    const int lr = lane & 15, lk = (lane >> 4) * 8;
    const int qr = lane >> 2, qc = (lane & 3) * 2;
    const int m0 = wid * 16;
    const int b = blockIdx.y, p0 = blockIdx.x * 128;
    const float* R = g_res + (size_t)b * CH * HW;   // [128 c][4096 p] view

    // ---- split res tile [128][128] ----
#pragma unroll 4
    for (int i = tid; i < 128 * 32; i += 256) {
        int c = i >> 5, p4 = (i & 31) * 4;
        float4 v = *(const float4*)&R[(size_t)c * HW + p0 + p4];
        uint32_t h0, l0, h1, l1;
        bfsplit2(v.x, v.y, h0, l0);
        bfsplit2(v.z, v.w, h1, l1);
        uint32_t o = off256(c, p4);
        *(uint32_t*)(sm + OS_RH + o) = h0;
        *(uint32_t*)(sm + OS_RL + o) = l0;
        *(uint32_t*)(sm + OS_RH + o + 4) = h1;
        *(uint32_t*)(sm + OS_RL + o + 4) = l1;
    }
    // ---- split full w4 [256][128] ----
#pragma unroll 4
    for (int i = tid; i < 256 * 32; i += 256) {
        int oo = i >> 5, c4 = (i & 31) * 4;
        float4 v = *(const float4*)&w4[oo * CH + c4];
        uint32_t h0, l0, h1, l1;
        bfsplit2(v.x, v.y, h0, l0);
        bfsplit2(v.z, v.w, h1, l1);
        uint32_t o = off256(oo, c4);
        *(uint32_t*)(sm + OS_WH + o) = h0;
        *(uint32_t*)(sm + OS_WL + o) = l0;
        *(uint32_t*)(sm + OS_WH + o + 4) = h1;
        *(uint32_t*)(sm + OS_WL + o + 4) = l1;
    }
    __syncthreads();

#pragma unroll 1
    for (int ot = 0; ot < 2; ot++) {
        float acc[16][4];
#pragma unroll
        for (int n = 0; n < 16; n++)
#pragma unroll
            for (int k = 0; k < 4; k++) acc[n][k] = 0.f;

#pragma unroll
        for (int ks = 0; ks < 8; ks++) {
            uint32_t ah[4], al[4];
            uint32_t aoff = off256(ot * 128 + m0 + lr, ks * 16 + lk);
            ldsm4(ah, smb + OS_WH + aoff);
            ldsm4(al, smb + OS_WL + aoff);
#pragma unroll
            for (int jg = 0; jg < 8; jg++) {
                uint32_t bh[4], bl[4];
                uint32_t boff = off256(ks * 16 + lr, jg * 16 + lk);
                ldsm4t(bh, smb + OS_RH + boff);
                ldsm4t(bl, smb + OS_RL + boff);
                mma16816(acc[jg*2],   ah, bh[0], bh[1]);
                mma16816(acc[jg*2+1], ah, bh[2], bh[3]);
                mma16816(acc[jg*2],   ah, bl[0], bl[1]);
                mma16816(acc[jg*2+1], ah, bl[2], bl[3]);
                mma16816(acc[jg*2],   al, bh[0], bh[1]);
                mma16816(acc[jg*2+1], al, bh[2], bh[3]);
            }
        }

        // ---- epilogue: BN + residual ----
        int oc1 = ot * 128 + m0 + qr, oc2 = oc1 + 8;
        float sc1 = gamma[oc1] * rsqrtf(rvar[oc1] + 1e-5f);
        float sc2 = gamma[oc2] * rsqrtf(rvar[oc2] + 1e-5f);
        float mu1 = rmean[oc1], bt1 = beta[oc1];
        float mu2 = rmean[oc2], bt2 = beta[oc2];
        size_t b1 = (size_t)b * CIN * HW + (size_t)oc1 * HW + p0;
        size_t b2 = (size_t)b * CIN * HW + (size_t)oc2 * HW + p0;
#pragma unroll
        for (int nb = 0; nb < 16; nb++) {
            int col = nb * 8 + qc;
            float2 xv1 = *(const float2*)&x[b1 + col];
            float2 xv2 = *(const float2*)&x[b2 + col];
            float2 o1 = make_float2((acc[nb][0] - mu1) * sc1 + bt1 + xv1.x,
                                    (acc[nb][1] - mu1) * sc1 + bt1 + xv1.y);
            float2 o2 = make_float2((acc[nb][2] - mu2) * sc2 + bt2 + xv2.x,
                                    (acc[nb][3] - mu2) * sc2 + bt2 + xv2.y);
            *(float2*)&out[b1 + col] = o1;
            *(float2*)&out[b2 + col] = o2;
        }
    }
}

// ---------------------------------------------------------------------------
extern "C" void kernel_launch(void* const* d_in, const int* in_sizes, int n_in,
                              void* d_out, int out_size) {
    const float* x     = (const float*)d_in[0];
    const float* w1    = (const float*)d_in[1];
    const float* w2    = (const float*)d_in[2];
    const float* w3    = (const float*)d_in[3];
    const float* w4    = (const float*)d_in[4];
    const float* gamma = (const float*)d_in[5];
    const float* beta  = (const float*)d_in[6];
    const float* rmean = (const float*)d_in[7];
    const float* rvar  = (const float*)d_in[8];
    float* out = (float*)d_out;

    cudaFuncSetAttribute(qkv_mma,
                         cudaFuncAttributeMaxDynamicSharedMemorySize, QKV_SMEM);
    qkv_mma<<<dim3(32, NB), 256, QKV_SMEM>>>(x, w1, w2, w3);

    cudaFuncSetAttribute(flash_mma,
                         cudaFuncAttributeMaxDynamicSharedMemorySize, FLASH_SMEM);
    flash_mma<<<dim3(32, NB), 256, FLASH_SMEM>>>();

    cudaFuncSetAttribute(out_mma,
                         cudaFuncAttributeMaxDynamicSharedMemorySize, OUT_SMEM);
    out_mma<<<dim3(32, NB), 256, OUT_SMEM>>>(x, w4, gamma, beta, rmean, rvar, out);
}